// round 9
// baseline (speedup 1.0000x reference)
#include <cuda_runtime.h>
#include <cuda_bf16.h>
#include <math.h>
#include <stdint.h>

#define Ldim 2048
#define Nb   4
#define E    768
#define H    12
#define HD   64
#define BH   (Nb*H)         /* 48 */
#define Mrows (Ldim*Nb)     /* 8192 */
#define EE   (E*E)          /* 589824 */
#define MK   (Mrows*E)      /* 6291456 */

// ---------------- scratch (static device globals; no runtime allocation) ----
__device__ float g_q[MK];
__device__ float g_k[MK];
__device__ float g_v[MK];
// bf16 hi/lo split weights [z][e][k] and activations [z][m][k]
__device__ __nv_bfloat16 g_wh[4*EE], g_wl[4*EE];
__device__ __nv_bfloat16 g_xh[3*MK], g_xl[3*MK];
__device__ __nv_bfloat16 g_oh[MK],  g_ol[MK];
// attention operand buffers: q,k as [bh][l][64]; v transposed as [bh][d][L]
__device__ __nv_bfloat16 g_qh[BH*Ldim*HD], g_ql[BH*Ldim*HD];
__device__ __nv_bfloat16 g_kh[BH*Ldim*HD], g_kl[BH*Ldim*HD];
__device__ __nv_bfloat16 g_vth[BH*HD*Ldim], g_vtl[BH*HD*Ldim];

// ============================ helpers ========================================
__device__ __forceinline__ uint32_t smem_u32(const void* p) {
    uint32_t a;
    asm("{ .reg .u64 t; cvta.to.shared.u64 t, %1; cvt.u32.u64 %0, t; }"
        : "=r"(a) : "l"(p));
    return a;
}
__device__ __forceinline__ float ex2f(float x) {
    float y; asm("ex2.approx.f32 %0, %1;" : "=f"(y) : "f"(x)); return y;
}
#define STS128(addr, r0, r1, r2, r3) \
    asm volatile("st.shared.v4.b32 [%0], {%1, %2, %3, %4};" \
                 :: "r"(addr), "r"(r0), "r"(r1), "r"(r2), "r"(r3) : "memory")

__device__ __forceinline__ void cpa16(uint32_t dst, const void* src) {
    asm volatile("cp.async.cg.shared.global [%0], [%1], 16;"
                 :: "r"(dst), "l"(src) : "memory");
}
#define CP_COMMIT() asm volatile("cp.async.commit_group;" ::: "memory")
#define CP_WAIT1()  asm volatile("cp.async.wait_group 1;" ::: "memory")
#define CP_WAIT0()  asm volatile("cp.async.wait_group 0;" ::: "memory")

__device__ __forceinline__ void ldm_x4(uint32_t* r, uint32_t addr) {
    asm volatile("ldmatrix.sync.aligned.m8n8.x4.shared.b16 {%0,%1,%2,%3}, [%4];"
                 : "=r"(r[0]), "=r"(r[1]), "=r"(r[2]), "=r"(r[3]) : "r"(addr));
}
__device__ __forceinline__ void mma16816(float* c, const uint32_t* a,
                                         const uint32_t* b) {
    asm volatile(
        "mma.sync.aligned.m16n8k16.row.col.f32.bf16.bf16.f32 "
        "{%0,%1,%2,%3}, {%4,%5,%6,%7}, {%8,%9}, {%0,%1,%2,%3};"
        : "+f"(c[0]), "+f"(c[1]), "+f"(c[2]), "+f"(c[3])
        : "r"(a[0]), "r"(a[1]), "r"(a[2]), "r"(a[3]), "r"(b[0]), "r"(b[1]));
}
// split a pair of floats into bf16 hi and lo packed words (elem0 in low bits)
__device__ __forceinline__ void split2(float a, float b, uint32_t& hi, uint32_t& lo) {
    __nv_bfloat162 h = __floats2bfloat162_rn(a, b);
    float la = a - __bfloat162float(h.x);
    float lb = b - __bfloat162float(h.y);
    __nv_bfloat162 l = __floats2bfloat162_rn(la, lb);
    hi = *reinterpret_cast<uint32_t*>(&h);
    lo = *reinterpret_cast<uint32_t*>(&l);
}

// ---------------- combined: W_eff split + x split ----------------------------
#define WEFF_BLOCKS 4608            /* 4 * EE/2 / 256 */
#define XSPL_BLOCKS 18432           /* 3 * MK/4 / 256 */

__global__ void __launch_bounds__(256) weff_split_kernel(
    const float* __restrict__ inW,  const float* __restrict__ outW,
    const float* __restrict__ qd, const float* __restrict__ qu,
    const float* __restrict__ kd, const float* __restrict__ ku,
    const float* __restrict__ vd, const float* __restrict__ vu,
    const float* __restrict__ od, const float* __restrict__ ou,
    const float* __restrict__ query, const float* __restrict__ key,
    const float* __restrict__ value)
{
    int bx = blockIdx.x;
    if (bx < WEFF_BLOCKS) {
        int z = bx / (WEFF_BLOCKS / 4);
        int pidx = (bx % (WEFF_BLOCKS / 4)) * 256 + threadIdx.x;  // pair idx < EE/2
        int e = (pidx * 2) / E;
        int k = (pidx * 2) % E;
        const float* W  = (z < 3) ? (inW + z * EE) : outW;
        const float* dn = (z == 0) ? qd : (z == 1) ? kd : (z == 2) ? vd : od;
        const float* up = (z == 0) ? qu : (z == 1) ? ku : (z == 2) ? vu : ou;
        float s0 = 0.f, s1 = 0.f;
#pragma unroll
        for (int r = 0; r < 16; r++) {
            float u = up[e * 16 + r];
            s0 += u * dn[r * E + k];
            s1 += u * dn[r * E + k + 1];
        }
        float v0 = W[e * E + k] + s0;
        float v1 = W[e * E + k + 1] + s1;
        uint32_t hi, lo;
        split2(v0, v1, hi, lo);
        ((uint32_t*)g_wh)[(size_t)z * (EE / 2) + pidx] = hi;
        ((uint32_t*)g_wl)[(size_t)z * (EE / 2) + pidx] = lo;
    } else {
        int i = bx - WEFF_BLOCKS;
        int z = i / (XSPL_BLOCKS / 3);
        size_t idx = (size_t)(i % (XSPL_BLOCKS / 3)) * 256 + threadIdx.x;  // float4 idx
        const float4* src = (const float4*)((z == 0) ? query : (z == 1) ? key : value);
        float4 v = src[idx];
        uint32_t h0, l0, h1, l1;
        split2(v.x, v.y, h0, l0);
        split2(v.z, v.w, h1, l1);
        size_t w = (size_t)z * (MK / 4) + idx;
        ((uint2*)g_xh)[w] = make_uint2(h0, h1);
        ((uint2*)g_xl)[w] = make_uint2(l0, l1);
    }
}

// ================= bf16 3-pass MMA GEMM ======================================
#define SKG 80                 /* smem row stride bytes (32 bf16 + pad) */
#define GA_H 0
#define GA_L 10240
#define GB_H 20480
#define GB_L 30720
#define GSTG 40960
#define G_SMEM (2*GSTG)        /* 81920 */
#define GKT (E/32)             /* 24 k-stages */

__device__ __forceinline__ void g_prefetch(
    uint32_t buf,
    const __nv_bfloat16* axh, const __nv_bfloat16* axl,
    const __nv_bfloat16* bwh, const __nv_bfloat16* bwl,
    int m0, int e0, int k0, int tid)
{
    int row = tid >> 1, part = tid & 1;
    uint32_t ro = (uint32_t)row * SKG + (uint32_t)part * 32;
    const __nv_bfloat16* ah = axh + (size_t)(m0 + row) * E + k0 + part * 16;
    const __nv_bfloat16* al = axl + (size_t)(m0 + row) * E + k0 + part * 16;
    const __nv_bfloat16* bh = bwh + (size_t)(e0 + row) * E + k0 + part * 16;
    const __nv_bfloat16* bl = bwl + (size_t)(e0 + row) * E + k0 + part * 16;
    cpa16(buf + GA_H + ro,      ah); cpa16(buf + GA_H + ro + 16, ah + 8);
    cpa16(buf + GA_L + ro,      al); cpa16(buf + GA_L + ro + 16, al + 8);
    cpa16(buf + GB_H + ro,      bh); cpa16(buf + GB_H + ro + 16, bh + 8);
    cpa16(buf + GB_L + ro,      bl); cpa16(buf + GB_L + ro + 16, bl + 8);
}

__global__ void __launch_bounds__(256) gemm_mma(
    const __nv_bfloat16* __restrict__ xh, const __nv_bfloat16* __restrict__ xl,
    const __nv_bfloat16* __restrict__ wh, const __nv_bfloat16* __restrict__ wl,
    const float* __restrict__ bias_base,
    float* __restrict__ y0, float* __restrict__ y1, float* __restrict__ y2,
    int qz)
{
    extern __shared__ __align__(128) char smem[];
    uint32_t sb = smem_u32(smem);
    int z = blockIdx.z;
    const __nv_bfloat16* axh = xh + (size_t)z * MK;
    const __nv_bfloat16* axl = xl + (size_t)z * MK;
    const __nv_bfloat16* bwh = wh + (size_t)z * EE;
    const __nv_bfloat16* bwl = wl + (size_t)z * EE;
    float* y = (z == 0) ? y0 : (z == 1) ? y1 : y2;
    const float* bias = bias_base + z * E;
    int m0 = blockIdx.y * 128, e0 = blockIdx.x * 128;
    int tid = threadIdx.x, wid = tid >> 5, lane = tid & 31;
    int wm = wid & 1, wn = wid >> 1;

    uint32_t arow = (uint32_t)(wm * 64 + (lane & 15)) * SKG + (uint32_t)(lane >> 4) * 16;
    uint32_t brow = (uint32_t)(wn * 32 + (lane >> 4) * 8 + (lane & 7)) * SKG
                  + (uint32_t)((lane >> 3) & 1) * 16;

    float acc[4][4][4];
#pragma unroll
    for (int a = 0; a < 4; a++)
#pragma unroll
        for (int b = 0; b < 4; b++)
#pragma unroll
            for (int c = 0; c < 4; c++) acc[a][b][c] = 0.f;

    g_prefetch(sb, axh, axl, bwh, bwl, m0, e0, 0, tid);
    CP_COMMIT();

    for (int kt = 0; kt < GKT; kt++) {
        uint32_t cb = sb + (uint32_t)(kt & 1) * GSTG;
        if (kt + 1 < GKT) {
            g_prefetch(sb + (uint32_t)((kt + 1) & 1) * GSTG,
                       axh, axl, bwh, bwl, m0, e0, (kt + 1) * 32, tid);
            CP_COMMIT();
            CP_WAIT1();
        } else {
            CP_WAIT0();
        }
        __syncthreads();
#pragma unroll
        for (int ks = 0; ks < 2; ks++) {
            uint32_t koff = (uint32_t)ks * 32;
            uint32_t bhf[2][4], blf[2][4];
            ldm_x4(bhf[0], cb + GB_H + brow + koff);
            ldm_x4(bhf[1], cb + GB_H + brow + 16 * SKG + koff);
            ldm_x4(blf[0], cb + GB_L + brow + koff);
            ldm_x4(blf[1], cb + GB_L + brow + 16 * SKG + koff);
#pragma unroll
            for (int mi = 0; mi < 4; mi++) {
                uint32_t ah[4], al[4];
                ldm_x4(ah, cb + GA_H + arow + mi * 16 * SKG + koff);
                ldm_x4(al, cb + GA_L + arow + mi * 16 * SKG + koff);
#pragma unroll
                for (int ni = 0; ni < 4; ni++) {
                    const uint32_t* bfh = bhf[ni >> 1] + (ni & 1) * 2;
                    const uint32_t* bfl = blf[ni >> 1] + (ni & 1) * 2;
                    mma16816(acc[mi][ni], ah, bfh);
                    mma16816(acc[mi][ni], ah, bfl);
                    mma16816(acc[mi][ni], al, bfh);
                }
            }
        }
        __syncthreads();
    }

    float qs = (z == qz) ? 0.125f * 1.4426950408889634f : 1.0f;
    int r = lane >> 2, cp = (lane & 3) * 2;
#pragma unroll
    for (int mi = 0; mi < 4; mi++) {
        int row0 = m0 + wm * 64 + mi * 16 + r;
#pragma unroll
        for (int ni = 0; ni < 4; ni++) {
            int col = e0 + wn * 32 + ni * 8 + cp;
            float b0 = bias[col], b1 = bias[col + 1];
            float2 v0 = make_float2((acc[mi][ni][0] + b0) * qs,
                                    (acc[mi][ni][1] + b1) * qs);
            float2 v1 = make_float2((acc[mi][ni][2] + b0) * qs,
                                    (acc[mi][ni][3] + b1) * qs);
            *(float2*)(y + (size_t)row0 * E + col) = v0;
            *(float2*)(y + (size_t)(row0 + 8) * E + col) = v1;
        }
    }
}

// ---------------- combined prep: qk split + v transpose ----------------------
#define QK_BLOCKS 12288   /* 2 * MK/4/256 */
#define PREP_BLOCKS (QK_BLOCKS + (Ldim/64)*BH)

__global__ void __launch_bounds__(256) prep_kernel()
{
    int bx = blockIdx.x;
    if (bx < QK_BLOCKS) {
        int z = bx / (QK_BLOCKS / 2);
        size_t idx = (size_t)(bx % (QK_BLOCKS / 2)) * 256 + threadIdx.x;
        const float4* src = (const float4*)(z ? g_k : g_q);
        float4 v = src[idx];
        int e4 = (int)(idx % (E / 4));
        int ln = (int)(idx / (E / 4));          // l*Nb + nb
        int e = e4 * 4, h = e >> 6, d = e & 63;
        int l = ln >> 2, nb = ln & 3;
        size_t dst = ((size_t)(nb * H + h) * Ldim + l) * HD + d;
        uint32_t h0, l0, h1, l1;
        split2(v.x, v.y, h0, l0);
        split2(v.z, v.w, h1, l1);
        __nv_bfloat16* dh = z ? g_kh : g_qh;
        __nv_bfloat16* dl = z ? g_kl : g_ql;
        *(uint2*)(dh + dst) = make_uint2(h0, h1);
        *(uint2*)(dl + dst) = make_uint2(l0, l1);
    } else {
        __shared__ float vt[64][65];
        int i = bx - QK_BLOCKS;
        int s0 = (i & 31) * 64;
        int bh = i >> 5;
        int nb = bh / H, h = bh % H;
        int t = threadIdx.x;
        {
            int s = t >> 2, dq = (t & 3) * 16;
            const float* src = g_v + ((size_t)(s0 + s) * Nb + nb) * E + h * HD + dq;
#pragma unroll
            for (int j = 0; j < 4; j++) {
                float4 v = *(const float4*)(src + j * 4);
                vt[s][dq + j * 4 + 0] = v.x;
                vt[s][dq + j * 4 + 1] = v.y;
                vt[s][dq + j * 4 + 2] = v.z;
                vt[s][dq + j * 4 + 3] = v.w;
            }
        }
        __syncthreads();
        {
            int d = t >> 2, sq = (t & 3) * 16;
            uint32_t hw[8], lw[8];
#pragma unroll
            for (int j = 0; j < 8; j++)
                split2(vt[sq + 2 * j][d], vt[sq + 2 * j + 1][d], hw[j], lw[j]);
            size_t dst = ((size_t)bh * HD + d) * Ldim + s0 + sq;
            ((uint4*)(g_vth + dst))[0] = make_uint4(hw[0], hw[1], hw[2], hw[3]);
            ((uint4*)(g_vth + dst))[1] = make_uint4(hw[4], hw[5], hw[6], hw[7]);
            ((uint4*)(g_vtl + dst))[0] = make_uint4(lw[0], lw[1], lw[2], lw[3]);
            ((uint4*)(g_vtl + dst))[1] = make_uint4(lw[4], lw[5], lw[6], lw[7]);
        }
    }
}

// ================= warp-MMA flash attention ==================================
// grid (L/64, BH), 128 threads (4 warps, 16 q-rows each), BS=64.
// Q staged through stage-1 buffer -> smem = 2 stages only = 72KB -> 3 CTAs/SM.
// Epilogue writes bf16 hi/lo O directly (fused o-split).
#define SKB 144
#define STAGE_B 36864
#define KH_O 0
#define KL_O 9216
#define VH_O 18432
#define VL_O 27648
#define S_TOTAL3 (2*STAGE_B)   /* 73728 */
#define NT (Ldim / 64)

__device__ __forceinline__ void kv_prefetch(uint32_t buf, int bh, int s0, int tid)
{
    int m = tid >> 1;
    int hf = tid & 1;
    uint32_t ro = (uint32_t)m * SKB + (uint32_t)hf * 64;
    const __nv_bfloat16* kh = g_kh + ((size_t)bh * Ldim + s0 + m) * HD + hf * 32;
    const __nv_bfloat16* kl = g_kl + ((size_t)bh * Ldim + s0 + m) * HD + hf * 32;
    const __nv_bfloat16* vh = g_vth + ((size_t)bh * HD + m) * Ldim + s0 + hf * 32;
    const __nv_bfloat16* vl = g_vtl + ((size_t)bh * HD + m) * Ldim + s0 + hf * 32;
#pragma unroll
    for (int c = 0; c < 4; c++) {
        cpa16(buf + KH_O + ro + c * 16, kh + c * 8);
        cpa16(buf + KL_O + ro + c * 16, kl + c * 8);
        cpa16(buf + VH_O + ro + c * 16, vh + c * 8);
        cpa16(buf + VL_O + ro + c * 16, vl + c * 8);
    }
}

__global__ void __launch_bounds__(128, 3) attn_mma3()
{
    extern __shared__ __align__(128) char smem[];
    uint32_t sb = smem_u32(smem);
    int tid = threadIdx.x;
    int wid = tid >> 5, lane = tid & 31;
    int bh = blockIdx.y;
    int nb = bh / H, h = bh % H;
    int q0 = blockIdx.x * 64;

    // stage-0 KV prefetch (into buffer 0)
    kv_prefetch(sb, bh, 0, tid);
    CP_COMMIT();

    // stage Q through buffer 1 (transient; fragments extracted to registers)
    {
        uint32_t qh_s = sb + STAGE_B;          // Q hi in stage-1 area
        uint32_t ql_s = sb + STAGE_B + 9216;   // Q lo
        int m = tid >> 1;
        int u0 = (tid & 1) * 4;
        uint32_t o = (uint32_t)m * SKB + (uint32_t)u0 * 16;
        const uint4* s = (const uint4*)(g_qh + ((size_t)bh * Ldim + q0 + m) * HD) + u0;
        uint4 a = s[0], b = s[1], c = s[2], d = s[3];
        STS128(qh_s + o,      a.x, a.y, a.z, a.w);
        STS128(qh_s + o + 16, b.x, b.y, b.z, b.w);
        STS128(qh_s + o + 32, c.x, c.y, c.z, c.w);
        STS128(qh_s + o + 48, d.x, d.y, d.z, d.w);
        s = (const uint4*)(g_ql + ((size_t)bh * Ldim + q0 + m) * HD) + u0;
        a = s[0]; b = s[1]; c = s[2]; d = s[3];
        STS128(ql_s + o,      a.x, a.y, a.z, a.w);
        STS128(ql_s + o + 16, b.x, b.y, b.z, b.w);
        STS128(ql_s + o + 32, c.x, c.y, c.z, c.w);
        STS128(ql_s + o + 48, d.x, d.y, d.z, d.w);
    }
    __syncthreads();

    uint32_t qrow = (uint32_t)(16 * wid + (lane & 15)) * SKB + (uint32_t)(lane >> 4) * 16;
    uint32_t brow = (uint32_t)(((lane >> 4) * 8 + (lane & 7))) * SKB
                  + (uint32_t)((lane >> 3) & 1) * 16;

    // Q fragments -> registers (then stage-1 buffer is free for KV)
    uint32_t qfh[4][4], qfl[4][4];
#pragma unroll
    for (int k = 0; k < 4; k++) {
        ldm_x4(qfh[k], sb + STAGE_B + qrow + k * 32);
        ldm_x4(qfl[k], sb + STAGE_B + 9216 + qrow + k * 32);
    }
    __syncthreads();   // all warps done reading Q before stage-1 prefetch

    float Oa[8][4];
#pragma unroll
    for (int n = 0; n < 8; n++)
#pragma unroll
        for (int j = 0; j < 4; j++) Oa[n][j] = 0.f;
    float m_lo = -INFINITY, m_hi = -INFINITY, l_lo = 0.f, l_hi = 0.f;

    for (int t = 0; t < NT; t++) {
        uint32_t cb = sb + (uint32_t)(t & 1) * STAGE_B;
        if (t + 1 < NT) {
            kv_prefetch(sb + (uint32_t)((t + 1) & 1) * STAGE_B,
                        bh, (t + 1) * 64, tid);
            CP_COMMIT();
            CP_WAIT1();
        } else {
            CP_WAIT0();
        }
        __syncthreads();

        // ---- S = Q K^T (3-pass) --------------------------------------------
        float c[8][4];
#pragma unroll
        for (int n = 0; n < 8; n++)
#pragma unroll
            for (int j = 0; j < 4; j++) c[n][j] = 0.f;
#pragma unroll
        for (int np = 0; np < 4; np++) {
            uint32_t baseH = cb + KH_O + brow + np * (16 * SKB);
            uint32_t baseL = cb + KL_O + brow + np * (16 * SKB);
#pragma unroll
            for (int k = 0; k < 4; k++) {
                uint32_t bhh[4], bll[4];
                ldm_x4(bhh, baseH + k * 32);
                ldm_x4(bll, baseL + k * 32);
                mma16816(c[2 * np],     qfh[k], bhh);
                mma16816(c[2 * np],     qfh[k], bll);
                mma16816(c[2 * np],     qfl[k], bhh);
                mma16816(c[2 * np + 1], qfh[k], bhh + 2);
                mma16816(c[2 * np + 1], qfh[k], bll + 2);
                mma16816(c[2 * np + 1], qfl[k], bhh + 2);
            }
        }

        // ---- online softmax (quad-local rows) -------------------------------
        float mn_lo = m_lo, mn_hi = m_hi;
#pragma unroll
        for (int n = 0; n < 8; n++) {
            mn_lo = fmaxf(mn_lo, fmaxf(c[n][0], c[n][1]));
            mn_hi = fmaxf(mn_hi, fmaxf(c[n][2], c[n][3]));
        }
        mn_lo = fmaxf(mn_lo, __shfl_xor_sync(0xffffffffu, mn_lo, 1));
        mn_lo = fmaxf(mn_lo, __shfl_xor_sync(0xffffffffu, mn_lo, 2));
        mn_hi = fmaxf(mn_hi, __shfl_xor_sync(0xffffffffu, mn_hi, 1));
        mn_hi = fmaxf(mn_hi, __shfl_xor_sync(0xffffffffu, mn_hi, 2));
        float corr_lo = ex2f(m_lo - mn_lo);
        float corr_hi = ex2f(m_hi - mn_hi);
        m_lo = mn_lo; m_hi = mn_hi;
        l_lo *= corr_lo; l_hi *= corr_hi;
#pragma unroll
        for (int n = 0; n < 8; n++) {
            Oa[n][0] *= corr_lo; Oa[n][1] *= corr_lo;
            Oa[n][2] *= corr_hi; Oa[n][3] *= corr_hi;
        }
        uint32_t ph[4][4], pl[4][4];
#pragma unroll
        for (int n = 0; n < 8; n++) {
            float p0 = ex2f(c[n][0] - mn_lo);
            float p1 = ex2f(c[n][1] - mn_lo);
            float p2 = ex2f(c[n][2] - mn_hi);
            float p3 = ex2f(c[n][3] - mn_hi);
            l_lo += p0 + p1;
            l_hi += p2 + p3;
            uint32_t h01, l01, h23, l23;
            split2(p0, p1, h01, l01);
            split2(p2, p3, h23, l23);
            int kc = n >> 1, o = (n & 1) * 2;
            ph[kc][o] = h01; ph[kc][o + 1] = h23;
            pl[kc][o] = l01; pl[kc][o + 1] = l23;
        }

        // ---- O += P V (3-pass) ----------------------------------------------
#pragma unroll
        for (int np = 0; np < 4; np++) {
            uint32_t baseH = cb + VH_O + brow + np * (16 * SKB);
            uint32_t baseL = cb + VL_O + brow + np * (16 * SKB);
#pragma unroll
            for (int k = 0; k < 4; k++) {
                uint32_t vhh[4], vll[4];
                ldm_x4(vhh, baseH + k * 32);
                ldm_x4(vll, baseL + k * 32);
                mma16816(Oa[2 * np],     ph[k], vhh);
                mma16816(Oa[2 * np],     ph[k], vll);
                mma16816(Oa[2 * np],     pl[k], vhh);
                mma16816(Oa[2 * np + 1], ph[k], vhh + 2);
                mma16816(Oa[2 * np + 1], ph[k], vll + 2);
                mma16816(Oa[2 * np + 1], pl[k], vhh + 2);
            }
        }
        __syncthreads();
    }

    // ---- epilogue: normalize + fused bf16 hi/lo split write -----------------
    l_lo += __shfl_xor_sync(0xffffffffu, l_lo, 1);
    l_lo += __shfl_xor_sync(0xffffffffu, l_lo, 2);
    l_hi += __shfl_xor_sync(0xffffffffu, l_hi, 1);
    l_hi += __shfl_xor_sync(0xffffffffu, l_hi, 2);
    float inv_lo = 1.f / l_lo, inv_hi = 1.f / l_hi;

    int r = lane >> 2, cc = (lane & 3) * 2;
    size_t base_lo = ((size_t)(q0 + 16 * wid + r) * Nb + nb) * E + h * HD;
    size_t base_hi = ((size_t)(q0 + 16 * wid + r + 8) * Nb + nb) * E + h * HD;
#pragma unroll
    for (int n = 0; n < 8; n++) {
        int d = n * 8 + cc;
        uint32_t hA, lA, hB, lB;
        split2(Oa[n][0] * inv_lo, Oa[n][1] * inv_lo, hA, lA);
        split2(Oa[n][2] * inv_hi, Oa[n][3] * inv_hi, hB, lB);
        ((uint32_t*)g_oh)[(base_lo + d) >> 1] = hA;
        ((uint32_t*)g_ol)[(base_lo + d) >> 1] = lA;
        ((uint32_t*)g_oh)[(base_hi + d) >> 1] = hB;
        ((uint32_t*)g_ol)[(base_hi + d) >> 1] = lB;
    }
}

// ---------------- launcher ---------------------------------------------------
extern "C" void kernel_launch(void* const* d_in, const int* in_sizes, int n_in,
                              void* d_out, int out_size)
{
    const float* query = (const float*)d_in[0];
    const float* key   = (const float*)d_in[1];
    const float* value = (const float*)d_in[2];
    const float* in_w  = (const float*)d_in[3];
    const float* in_b  = (const float*)d_in[4];
    const float* q_dn  = (const float*)d_in[5];
    const float* q_up  = (const float*)d_in[6];
    const float* k_dn  = (const float*)d_in[7];
    const float* k_up  = (const float*)d_in[8];
    const float* v_dn  = (const float*)d_in[9];
    const float* v_up  = (const float*)d_in[10];
    const float* out_w = (const float*)d_in[11];
    const float* out_b = (const float*)d_in[12];
    const float* o_dn  = (const float*)d_in[13];
    const float* o_up  = (const float*)d_in[14];

    float *p_q, *p_k, *p_v;
    __nv_bfloat16 *p_wh, *p_wl, *p_xh, *p_xl, *p_oh, *p_ol;
    cudaGetSymbolAddress((void**)&p_q, g_q);
    cudaGetSymbolAddress((void**)&p_k, g_k);
    cudaGetSymbolAddress((void**)&p_v, g_v);
    cudaGetSymbolAddress((void**)&p_wh, g_wh);
    cudaGetSymbolAddress((void**)&p_wl, g_wl);
    cudaGetSymbolAddress((void**)&p_xh, g_xh);
    cudaGetSymbolAddress((void**)&p_xl, g_xl);
    cudaGetSymbolAddress((void**)&p_oh, g_oh);
    cudaGetSymbolAddress((void**)&p_ol, g_ol);

    cudaFuncSetAttribute(attn_mma3,
                         cudaFuncAttributeMaxDynamicSharedMemorySize, S_TOTAL3);
    cudaFuncSetAttribute(gemm_mma,
                         cudaFuncAttributeMaxDynamicSharedMemorySize, G_SMEM);

    // 1) W_eff -> bf16 hi/lo + input split
    weff_split_kernel<<<WEFF_BLOCKS + XSPL_BLOCKS, 256>>>(
        in_w, out_w, q_dn, q_up, k_dn, k_up, v_dn, v_up, o_dn, o_up,
        query, key, value);
    // 2) QKV projections via bf16 3-pass MMA (q pre-scaled by 0.125*log2e)
    gemm_mma<<<dim3(E / 128, Mrows / 128, 3), 256, G_SMEM>>>(
        p_xh, p_xl, p_wh, p_wl, in_b, p_q, p_k, p_v, /*qz=*/0);
    // 3) combined prep: q,k bf16 split + v transpose/split
    prep_kernel<<<PREP_BLOCKS, 256>>>();
    // 4) warp-MMA flash attention (launch #4 -> profiled); writes g_oh/g_ol
    attn_mma3<<<dim3(Ldim / 64, BH), 128, S_TOTAL3>>>();
    // 5) output projection via bf16 3-pass MMA -> d_out
    gemm_mma<<<dim3(E / 128, Mrows / 128, 1), 256, G_SMEM>>>(
        p_oh, p_ol, p_wh + 3 * (size_t)EE, p_wl + 3 * (size_t)EE, out_b,
        (float*)d_out, (float*)d_out, (float*)d_out, /*qz=*/-1);
}

// round 10
// speedup vs baseline: 1.3685x; 1.3685x over previous
#include <cuda_runtime.h>
#include <cuda_fp16.h>
#include <math.h>
#include <stdint.h>

#define Ldim 2048
#define Nb   4
#define E    768
#define H    12
#define HD   64
#define BH   (Nb*H)         /* 48 */
#define Mrows (Ldim*Nb)     /* 8192 */
#define EE   (E*E)          /* 589824 */
#define MK   (Mrows*E)      /* 6291456 */

// ---------------- scratch (static device globals; no runtime allocation) ----
__device__ float g_q[MK];
__device__ float g_k[MK];
__device__ float g_v[MK];
// fp16 operands: weights hi/lo [z][e][k]; activations single [z][m][k]
__device__ __half g_wh[4*EE], g_wl[4*EE];
__device__ __half g_xf[3*MK];
__device__ __half g_of[MK];
// attention operands: q single, k hi/lo as [bh][l][64]; v hi/lo transposed [bh][d][L]
__device__ __half g_qf[BH*Ldim*HD];
__device__ __half g_kh[BH*Ldim*HD], g_kl[BH*Ldim*HD];
__device__ __half g_vth[BH*HD*Ldim], g_vtl[BH*HD*Ldim];

// ============================ helpers ========================================
__device__ __forceinline__ uint32_t smem_u32(const void* p) {
    uint32_t a;
    asm("{ .reg .u64 t; cvta.to.shared.u64 t, %1; cvt.u32.u64 %0, t; }"
        : "=r"(a) : "l"(p));
    return a;
}
__device__ __forceinline__ float ex2f(float x) {
    float y; asm("ex2.approx.f32 %0, %1;" : "=f"(y) : "f"(x)); return y;
}
#define STS128(addr, r0, r1, r2, r3) \
    asm volatile("st.shared.v4.b32 [%0], {%1, %2, %3, %4};" \
                 :: "r"(addr), "r"(r0), "r"(r1), "r"(r2), "r"(r3) : "memory")

__device__ __forceinline__ void cpa16(uint32_t dst, const void* src) {
    asm volatile("cp.async.cg.shared.global [%0], [%1], 16;"
                 :: "r"(dst), "l"(src) : "memory");
}
#define CP_COMMIT() asm volatile("cp.async.commit_group;" ::: "memory")
#define CP_WAIT1()  asm volatile("cp.async.wait_group 1;" ::: "memory")
#define CP_WAIT0()  asm volatile("cp.async.wait_group 0;" ::: "memory")

__device__ __forceinline__ void ldm_x4(uint32_t* r, uint32_t addr) {
    asm volatile("ldmatrix.sync.aligned.m8n8.x4.shared.b16 {%0,%1,%2,%3}, [%4];"
                 : "=r"(r[0]), "=r"(r[1]), "=r"(r[2]), "=r"(r[3]) : "r"(addr));
}
// fp16 MMA, fp32 accumulate
__device__ __forceinline__ void mma16816(float* c, const uint32_t* a,
                                         const uint32_t* b) {
    asm volatile(
        "mma.sync.aligned.m16n8k16.row.col.f32.f16.f16.f32 "
        "{%0,%1,%2,%3}, {%4,%5,%6,%7}, {%8,%9}, {%0,%1,%2,%3};"
        : "+f"(c[0]), "+f"(c[1]), "+f"(c[2]), "+f"(c[3])
        : "r"(a[0]), "r"(a[1]), "r"(a[2]), "r"(a[3]), "r"(b[0]), "r"(b[1]));
}
// fp16 hi/lo split of a float pair (elem0 in low half)
__device__ __forceinline__ void split2h(float a, float b, uint32_t& hi, uint32_t& lo) {
    __half2 h = __floats2half2_rn(a, b);
    float2 hf = __half22float2(h);
    __half2 l = __floats2half2_rn(a - hf.x, b - hf.y);
    hi = *reinterpret_cast<uint32_t*>(&h);
    lo = *reinterpret_cast<uint32_t*>(&l);
}
__device__ __forceinline__ uint32_t pack2h(float a, float b) {
    __half2 h = __floats2half2_rn(a, b);
    return *reinterpret_cast<uint32_t*>(&h);
}

// ---------------- combined: W_eff fp16 split + x fp16 pack -------------------
#define WEFF_BLOCKS 4608            /* 4 * EE/2 / 256 */
#define XSPL_BLOCKS 18432           /* 3 * MK/4 / 256 */

__global__ void __launch_bounds__(256) weff_split_kernel(
    const float* __restrict__ inW,  const float* __restrict__ outW,
    const float* __restrict__ qd, const float* __restrict__ qu,
    const float* __restrict__ kd, const float* __restrict__ ku,
    const float* __restrict__ vd, const float* __restrict__ vu,
    const float* __restrict__ od, const float* __restrict__ ou,
    const float* __restrict__ query, const float* __restrict__ key,
    const float* __restrict__ value)
{
    int bx = blockIdx.x;
    if (bx < WEFF_BLOCKS) {
        int z = bx / (WEFF_BLOCKS / 4);
        int pidx = (bx % (WEFF_BLOCKS / 4)) * 256 + threadIdx.x;  // pair idx < EE/2
        int e = (pidx * 2) / E;
        int k = (pidx * 2) % E;
        const float* W  = (z < 3) ? (inW + z * EE) : outW;
        const float* dn = (z == 0) ? qd : (z == 1) ? kd : (z == 2) ? vd : od;
        const float* up = (z == 0) ? qu : (z == 1) ? ku : (z == 2) ? vu : ou;
        float s0 = 0.f, s1 = 0.f;
#pragma unroll
        for (int r = 0; r < 16; r++) {
            float u = up[e * 16 + r];
            s0 += u * dn[r * E + k];
            s1 += u * dn[r * E + k + 1];
        }
        float v0 = W[e * E + k] + s0;
        float v1 = W[e * E + k + 1] + s1;
        uint32_t hi, lo;
        split2h(v0, v1, hi, lo);
        ((uint32_t*)g_wh)[(size_t)z * (EE / 2) + pidx] = hi;
        ((uint32_t*)g_wl)[(size_t)z * (EE / 2) + pidx] = lo;
    } else {
        int i = bx - WEFF_BLOCKS;
        int z = i / (XSPL_BLOCKS / 3);
        size_t idx = (size_t)(i % (XSPL_BLOCKS / 3)) * 256 + threadIdx.x;  // float4 idx
        const float4* src = (const float4*)((z == 0) ? query : (z == 1) ? key : value);
        float4 v = src[idx];
        ((uint2*)g_xf)[(size_t)z * (MK / 4) + idx] =
            make_uint2(pack2h(v.x, v.y), pack2h(v.z, v.w));
    }
}

// ================= fp16 2-pass MMA GEMM ======================================
// y[m,e] = (sum_k x[m,k]*(Wh+Wl)[e,k] + bias[e]) * (z==qz ? qscale : 1)
// A single fp16, B hi/lo fp16. tiles 128x128x32, 256 threads, double buffer.
#define SKG 80                 /* smem row stride bytes (32 fp16 + pad) */
#define GA_F 0
#define GB_H 10240
#define GB_L 20480
#define GSTG 30720
#define G_SMEM (2*GSTG)        /* 61440 */
#define GKT (E/32)             /* 24 k-stages */

__device__ __forceinline__ void g_prefetch(
    uint32_t buf,
    const __half* axf, const __half* bwh, const __half* bwl,
    int m0, int e0, int k0, int tid)
{
    int row = tid >> 1, part = tid & 1;
    uint32_t ro = (uint32_t)row * SKG + (uint32_t)part * 32;
    const __half* af = axf + (size_t)(m0 + row) * E + k0 + part * 16;
    const __half* bh = bwh + (size_t)(e0 + row) * E + k0 + part * 16;
    const __half* bl = bwl + (size_t)(e0 + row) * E + k0 + part * 16;
    cpa16(buf + GA_F + ro,      af); cpa16(buf + GA_F + ro + 16, af + 8);
    cpa16(buf + GB_H + ro,      bh); cpa16(buf + GB_H + ro + 16, bh + 8);
    cpa16(buf + GB_L + ro,      bl); cpa16(buf + GB_L + ro + 16, bl + 8);
}

__global__ void __launch_bounds__(256) gemm_mma(
    const __half* __restrict__ xf,
    const __half* __restrict__ wh, const __half* __restrict__ wl,
    const float* __restrict__ bias_base,
    float* __restrict__ y0, float* __restrict__ y1, float* __restrict__ y2,
    int qz)
{
    extern __shared__ __align__(128) char smem[];
    uint32_t sb = smem_u32(smem);
    int z = blockIdx.z;
    const __half* axf = xf + (size_t)z * MK;
    const __half* bwh = wh + (size_t)z * EE;
    const __half* bwl = wl + (size_t)z * EE;
    float* y = (z == 0) ? y0 : (z == 1) ? y1 : y2;
    const float* bias = bias_base + z * E;
    int m0 = blockIdx.y * 128, e0 = blockIdx.x * 128;
    int tid = threadIdx.x, wid = tid >> 5, lane = tid & 31;
    int wm = wid & 1, wn = wid >> 1;

    uint32_t arow = (uint32_t)(wm * 64 + (lane & 15)) * SKG + (uint32_t)(lane >> 4) * 16;
    uint32_t brow = (uint32_t)(wn * 32 + (lane >> 4) * 8 + (lane & 7)) * SKG
                  + (uint32_t)((lane >> 3) & 1) * 16;

    float acc[4][4][4];
#pragma unroll
    for (int a = 0; a < 4; a++)
#pragma unroll
        for (int b = 0; b < 4; b++)
#pragma unroll
            for (int c = 0; c < 4; c++) acc[a][b][c] = 0.f;

    g_prefetch(sb, axf, bwh, bwl, m0, e0, 0, tid);
    CP_COMMIT();

    for (int kt = 0; kt < GKT; kt++) {
        uint32_t cb = sb + (uint32_t)(kt & 1) * GSTG;
        if (kt + 1 < GKT) {
            g_prefetch(sb + (uint32_t)((kt + 1) & 1) * GSTG,
                       axf, bwh, bwl, m0, e0, (kt + 1) * 32, tid);
            CP_COMMIT();
            CP_WAIT1();
        } else {
            CP_WAIT0();
        }
        __syncthreads();
#pragma unroll
        for (int ks = 0; ks < 2; ks++) {
            uint32_t koff = (uint32_t)ks * 32;
            uint32_t bhf[2][4], blf[2][4];
            ldm_x4(bhf[0], cb + GB_H + brow + koff);
            ldm_x4(bhf[1], cb + GB_H + brow + 16 * SKG + koff);
            ldm_x4(blf[0], cb + GB_L + brow + koff);
            ldm_x4(blf[1], cb + GB_L + brow + 16 * SKG + koff);
#pragma unroll
            for (int mi = 0; mi < 4; mi++) {
                uint32_t af[4];
                ldm_x4(af, cb + GA_F + arow + mi * 16 * SKG + koff);
#pragma unroll
                for (int ni = 0; ni < 4; ni++) {
                    const uint32_t* bfh = bhf[ni >> 1] + (ni & 1) * 2;
                    const uint32_t* bfl = blf[ni >> 1] + (ni & 1) * 2;
                    mma16816(acc[mi][ni], af, bfh);
                    mma16816(acc[mi][ni], af, bfl);
                }
            }
        }
        __syncthreads();
    }

    float qs = (z == qz) ? 0.125f * 1.4426950408889634f : 1.0f;
    int r = lane >> 2, cp = (lane & 3) * 2;
#pragma unroll
    for (int mi = 0; mi < 4; mi++) {
        int row0 = m0 + wm * 64 + mi * 16 + r;
#pragma unroll
        for (int ni = 0; ni < 4; ni++) {
            int col = e0 + wn * 32 + ni * 8 + cp;
            float b0 = bias[col], b1 = bias[col + 1];
            float2 v0 = make_float2((acc[mi][ni][0] + b0) * qs,
                                    (acc[mi][ni][1] + b1) * qs);
            float2 v1 = make_float2((acc[mi][ni][2] + b0) * qs,
                                    (acc[mi][ni][3] + b1) * qs);
            *(float2*)(y + (size_t)row0 * E + col) = v0;
            *(float2*)(y + (size_t)(row0 + 8) * E + col) = v1;
        }
    }
}

// ---------------- combined prep: q pack / k split + v transpose --------------
#define QK_BLOCKS 12288   /* 2 * MK/4/256 */
#define PREP_BLOCKS (QK_BLOCKS + (Ldim/64)*BH)

__global__ void __launch_bounds__(256) prep_kernel()
{
    int bx = blockIdx.x;
    if (bx < QK_BLOCKS) {
        int z = bx / (QK_BLOCKS / 2);
        size_t idx = (size_t)(bx % (QK_BLOCKS / 2)) * 256 + threadIdx.x;
        const float4* src = (const float4*)(z ? g_k : g_q);
        float4 v = src[idx];
        int e4 = (int)(idx % (E / 4));
        int ln = (int)(idx / (E / 4));          // l*Nb + nb
        int e = e4 * 4, h = e >> 6, d = e & 63;
        int l = ln >> 2, nb = ln & 3;
        size_t dst = ((size_t)(nb * H + h) * Ldim + l) * HD + d;
        if (z == 0) {
            *(uint2*)(g_qf + dst) = make_uint2(pack2h(v.x, v.y), pack2h(v.z, v.w));
        } else {
            uint32_t h0, l0, h1, l1;
            split2h(v.x, v.y, h0, l0);
            split2h(v.z, v.w, h1, l1);
            *(uint2*)(g_kh + dst) = make_uint2(h0, h1);
            *(uint2*)(g_kl + dst) = make_uint2(l0, l1);
        }
    } else {
        __shared__ float vt[64][65];
        int i = bx - QK_BLOCKS;
        int s0 = (i & 31) * 64;
        int bh = i >> 5;
        int nb = bh / H, h = bh % H;
        int t = threadIdx.x;
        {
            int s = t >> 2, dq = (t & 3) * 16;
            const float* src = g_v + ((size_t)(s0 + s) * Nb + nb) * E + h * HD + dq;
#pragma unroll
            for (int j = 0; j < 4; j++) {
                float4 v = *(const float4*)(src + j * 4);
                vt[s][dq + j * 4 + 0] = v.x;
                vt[s][dq + j * 4 + 1] = v.y;
                vt[s][dq + j * 4 + 2] = v.z;
                vt[s][dq + j * 4 + 3] = v.w;
            }
        }
        __syncthreads();
        {
            int d = t >> 2, sq = (t & 3) * 16;
            uint32_t hw[8], lw[8];
#pragma unroll
            for (int j = 0; j < 8; j++)
                split2h(vt[sq + 2 * j][d], vt[sq + 2 * j + 1][d], hw[j], lw[j]);
            size_t dst = ((size_t)bh * HD + d) * Ldim + s0 + sq;
            ((uint4*)(g_vth + dst))[0] = make_uint4(hw[0], hw[1], hw[2], hw[3]);
            ((uint4*)(g_vth + dst))[1] = make_uint4(hw[4], hw[5], hw[6], hw[7]);
            ((uint4*)(g_vtl + dst))[0] = make_uint4(lw[0], lw[1], lw[2], lw[3]);
            ((uint4*)(g_vtl + dst))[1] = make_uint4(lw[4], lw[5], lw[6], lw[7]);
        }
    }
}

// ================= warp-MMA flash attention (fp16 2-pass) ====================
// grid (L/64, BH), 128 threads. Q single fp16 (staged via stage-1 buffer),
// K hi/lo, V hi/lo. QK: qf*(kh+kl). PV: P-rounded-fp16*(vh+vl), exact-l norm.
#define SKB 144
#define STAGE_B 36864
#define KH_O 0
#define KL_O 9216
#define VH_O 18432
#define VL_O 27648
#define S_TOTAL3 (2*STAGE_B)   /* 73728 */
#define NT (Ldim / 64)

__device__ __forceinline__ void kv_prefetch(uint32_t buf, int bh, int s0, int tid)
{
    int m = tid >> 1;
    int hf = tid & 1;
    uint32_t ro = (uint32_t)m * SKB + (uint32_t)hf * 64;
    const __half* kh = g_kh + ((size_t)bh * Ldim + s0 + m) * HD + hf * 32;
    const __half* kl = g_kl + ((size_t)bh * Ldim + s0 + m) * HD + hf * 32;
    const __half* vh = g_vth + ((size_t)bh * HD + m) * Ldim + s0 + hf * 32;
    const __half* vl = g_vtl + ((size_t)bh * HD + m) * Ldim + s0 + hf * 32;
#pragma unroll
    for (int c = 0; c < 4; c++) {
        cpa16(buf + KH_O + ro + c * 16, kh + c * 8);
        cpa16(buf + KL_O + ro + c * 16, kl + c * 8);
        cpa16(buf + VH_O + ro + c * 16, vh + c * 8);
        cpa16(buf + VL_O + ro + c * 16, vl + c * 8);
    }
}

__global__ void __launch_bounds__(128, 3) attn_mma3()
{
    extern __shared__ __align__(128) char smem[];
    uint32_t sb = smem_u32(smem);
    int tid = threadIdx.x;
    int wid = tid >> 5, lane = tid & 31;
    int bh = blockIdx.y;
    int nb = bh / H, h = bh % H;
    int q0 = blockIdx.x * 64;

    // stage-0 KV prefetch (buffer 0)
    kv_prefetch(sb, bh, 0, tid);
    CP_COMMIT();

    // stage Q (single fp16) through stage-1 buffer
    {
        uint32_t q_s = sb + STAGE_B;
        int m = tid >> 1;
        int u0 = (tid & 1) * 4;
        uint32_t o = (uint32_t)m * SKB + (uint32_t)u0 * 16;
        const uint4* s = (const uint4*)(g_qf + ((size_t)bh * Ldim + q0 + m) * HD) + u0;
        uint4 a = s[0], b = s[1], c = s[2], d = s[3];
        STS128(q_s + o,      a.x, a.y, a.z, a.w);
        STS128(q_s + o + 16, b.x, b.y, b.z, b.w);
        STS128(q_s + o + 32, c.x, c.y, c.z, c.w);
        STS128(q_s + o + 48, d.x, d.y, d.z, d.w);
    }
    __syncthreads();

    uint32_t qrow = (uint32_t)(16 * wid + (lane & 15)) * SKB + (uint32_t)(lane >> 4) * 16;
    uint32_t brow = (uint32_t)(((lane >> 4) * 8 + (lane & 7))) * SKB
                  + (uint32_t)((lane >> 3) & 1) * 16;

    // Q fragments -> registers
    uint32_t qf[4][4];
#pragma unroll
    for (int k = 0; k < 4; k++)
        ldm_x4(qf[k], sb + STAGE_B + qrow + k * 32);
    __syncthreads();   // all warps done with Q before stage-1 prefetch

    float Oa[8][4];
#pragma unroll
    for (int n = 0; n < 8; n++)
#pragma unroll
        for (int j = 0; j < 4; j++) Oa[n][j] = 0.f;
    float m_lo = -INFINITY, m_hi = -INFINITY, l_lo = 0.f, l_hi = 0.f;

    for (int t = 0; t < NT; t++) {
        uint32_t cb = sb + (uint32_t)(t & 1) * STAGE_B;
        if (t + 1 < NT) {
            kv_prefetch(sb + (uint32_t)((t + 1) & 1) * STAGE_B,
                        bh, (t + 1) * 64, tid);
            CP_COMMIT();
            CP_WAIT1();
        } else {
            CP_WAIT0();
        }
        __syncthreads();

        // ---- S = Q (Kh + Kl)^T : 2-pass --------------------------------------
        float c[8][4];
#pragma unroll
        for (int n = 0; n < 8; n++)
#pragma unroll
            for (int j = 0; j < 4; j++) c[n][j] = 0.f;
#pragma unroll
        for (int np = 0; np < 4; np++) {
            uint32_t baseH = cb + KH_O + brow + np * (16 * SKB);
            uint32_t baseL = cb + KL_O + brow + np * (16 * SKB);
#pragma unroll
            for (int k = 0; k < 4; k++) {
                uint32_t bhh[4], bll[4];
                ldm_x4(bhh, baseH + k * 32);
                ldm_x4(bll, baseL + k * 32);
                mma16816(c[2 * np],     qf[k], bhh);
                mma16816(c[2 * np],     qf[k], bll);
                mma16816(c[2 * np + 1], qf[k], bhh + 2);
                mma16816(c[2 * np + 1], qf[k], bll + 2);
            }
        }

        // ---- online softmax (quad-local rows) -------------------------------
        float mn_lo = m_lo, mn_hi = m_hi;
#pragma unroll
        for (int n = 0; n < 8; n++) {
            mn_lo = fmaxf(mn_lo, fmaxf(c[n][0], c[n][1]));
            mn_hi = fmaxf(mn_hi, fmaxf(c[n][2], c[n][3]));
        }
        mn_lo = fmaxf(mn_lo, __shfl_xor_sync(0xffffffffu, mn_lo, 1));
        mn_lo = fmaxf(mn_lo, __shfl_xor_sync(0xffffffffu, mn_lo, 2));
        mn_hi = fmaxf(mn_hi, __shfl_xor_sync(0xffffffffu, mn_hi, 1));
        mn_hi = fmaxf(mn_hi, __shfl_xor_sync(0xffffffffu, mn_hi, 2));
        float corr_lo = ex2f(m_lo - mn_lo);
        float corr_hi = ex2f(m_hi - mn_hi);
        m_lo = mn_lo; m_hi = mn_hi;
        l_lo *= corr_lo; l_hi *= corr_hi;
#pragma unroll
        for (int n = 0; n < 8; n++) {
            Oa[n][0] *= corr_lo; Oa[n][1] *= corr_lo;
            Oa[n][2] *= corr_hi; Oa[n][3] *= corr_hi;
        }
        // exp -> round to fp16 P; accumulate l from ROUNDED values (exact norm)
        uint32_t ph[4][4];
#pragma unroll
        for (int n = 0; n < 8; n++) {
            float p0 = ex2f(c[n][0] - mn_lo);
            float p1 = ex2f(c[n][1] - mn_lo);
            float p2 = ex2f(c[n][2] - mn_hi);
            float p3 = ex2f(c[n][3] - mn_hi);
            __half2 h01 = __floats2half2_rn(p0, p1);
            __half2 h23 = __floats2half2_rn(p2, p3);
            float2 f01 = __half22float2(h01);
            float2 f23 = __half22float2(h23);
            l_lo += f01.x + f01.y;
            l_hi += f23.x + f23.y;
            int kc = n >> 1, o = (n & 1) * 2;
            ph[kc][o]     = *reinterpret_cast<uint32_t*>(&h01);
            ph[kc][o + 1] = *reinterpret_cast<uint32_t*>(&h23);
        }

        // ---- O += P (Vh + Vl) : 2-pass ---------------------------------------
#pragma unroll
        for (int np = 0; np < 4; np++) {
            uint32_t baseH = cb + VH_O + brow + np * (16 * SKB);
            uint32_t baseL = cb + VL_O + brow + np * (16 * SKB);
#pragma unroll
            for (int k = 0; k < 4; k++) {
                uint32_t vhh[4], vll[4];
                ldm_x4(vhh, baseH + k * 32);
                ldm_x4(vll, baseL + k * 32);
                mma16816(Oa[2 * np],     ph[k], vhh);
                mma16816(Oa[2 * np],     ph[k], vll);
                mma16816(Oa[2 * np + 1], ph[k], vhh + 2);
                mma16816(Oa[2 * np + 1], ph[k], vll + 2);
            }
        }
        __syncthreads();
    }

    // ---- epilogue: normalize + fp16 pack write -------------------------------
    l_lo += __shfl_xor_sync(0xffffffffu, l_lo, 1);
    l_lo += __shfl_xor_sync(0xffffffffu, l_lo, 2);
    l_hi += __shfl_xor_sync(0xffffffffu, l_hi, 1);
    l_hi += __shfl_xor_sync(0xffffffffu, l_hi, 2);
    float inv_lo = 1.f / l_lo, inv_hi = 1.f / l_hi;

    int r = lane >> 2, cc = (lane & 3) * 2;
    size_t base_lo = ((size_t)(q0 + 16 * wid + r) * Nb + nb) * E + h * HD;
    size_t base_hi = ((size_t)(q0 + 16 * wid + r + 8) * Nb + nb) * E + h * HD;
#pragma unroll
    for (int n = 0; n < 8; n++) {
        int d = n * 8 + cc;
        ((uint32_t*)g_of)[(base_lo + d) >> 1] =
            pack2h(Oa[n][0] * inv_lo, Oa[n][1] * inv_lo);
        ((uint32_t*)g_of)[(base_hi + d) >> 1] =
            pack2h(Oa[n][2] * inv_hi, Oa[n][3] * inv_hi);
    }
}

// ---------------- launcher ---------------------------------------------------
extern "C" void kernel_launch(void* const* d_in, const int* in_sizes, int n_in,
                              void* d_out, int out_size)
{
    const float* query = (const float*)d_in[0];
    const float* key   = (const float*)d_in[1];
    const float* value = (const float*)d_in[2];
    const float* in_w  = (const float*)d_in[3];
    const float* in_b  = (const float*)d_in[4];
    const float* q_dn  = (const float*)d_in[5];
    const float* q_up  = (const float*)d_in[6];
    const float* k_dn  = (const float*)d_in[7];
    const float* k_up  = (const float*)d_in[8];
    const float* v_dn  = (const float*)d_in[9];
    const float* v_up  = (const float*)d_in[10];
    const float* out_w = (const float*)d_in[11];
    const float* out_b = (const float*)d_in[12];
    const float* o_dn  = (const float*)d_in[13];
    const float* o_up  = (const float*)d_in[14];

    float *p_q, *p_k, *p_v;
    __half *p_wh, *p_wl, *p_xf, *p_of;
    cudaGetSymbolAddress((void**)&p_q, g_q);
    cudaGetSymbolAddress((void**)&p_k, g_k);
    cudaGetSymbolAddress((void**)&p_v, g_v);
    cudaGetSymbolAddress((void**)&p_wh, g_wh);
    cudaGetSymbolAddress((void**)&p_wl, g_wl);
    cudaGetSymbolAddress((void**)&p_xf, g_xf);
    cudaGetSymbolAddress((void**)&p_of, g_of);

    cudaFuncSetAttribute(attn_mma3,
                         cudaFuncAttributeMaxDynamicSharedMemorySize, S_TOTAL3);
    cudaFuncSetAttribute(gemm_mma,
                         cudaFuncAttributeMaxDynamicSharedMemorySize, G_SMEM);

    // 1) W_eff -> fp16 hi/lo + input fp16 pack
    weff_split_kernel<<<WEFF_BLOCKS + XSPL_BLOCKS, 256>>>(
        in_w, out_w, q_dn, q_up, k_dn, k_up, v_dn, v_up, o_dn, o_up,
        query, key, value);
    // 2) QKV projections via fp16 2-pass MMA (q pre-scaled by 0.125*log2e)
    gemm_mma<<<dim3(E / 128, Mrows / 128, 3), 256, G_SMEM>>>(
        p_xf, p_wh, p_wl, in_b, p_q, p_k, p_v, /*qz=*/0);
    // 3) combined prep: q fp16 pack / k fp16 split + v transpose/split
    prep_kernel<<<PREP_BLOCKS, 256>>>();
    // 4) warp-MMA flash attention (launch #4 -> profiled); writes g_of
    attn_mma3<<<dim3(Ldim / 64, BH), 128, S_TOTAL3>>>();
    // 5) output projection via fp16 2-pass MMA -> d_out
    gemm_mma<<<dim3(E / 128, Mrows / 128, 1), 256, G_SMEM>>>(
        p_of, p_wh + 3 * (size_t)EE, p_wl + 3 * (size_t)EE, out_b,
        (float*)d_out, (float*)d_out, (float*)d_out, /*qz=*/-1);
}

// round 11
// speedup vs baseline: 1.6068x; 1.1742x over previous
#include <cuda_runtime.h>
#include <cuda_fp16.h>
#include <math.h>
#include <stdint.h>

#define Ldim 2048
#define Nb   4
#define E    768
#define H    12
#define HD   64
#define BH   (Nb*H)         /* 48 */
#define Mrows (Ldim*Nb)     /* 8192 */
#define EE   (E*E)          /* 589824 */
#define MK   (Mrows*E)      /* 6291456 */

// ---------------- scratch (static device globals; no runtime allocation) ----
__device__ float g_q[MK];
__device__ float g_k[MK];
__device__ float g_v[MK];
// fp16 operands: weights hi/lo [z][e][k]; activations single [z][m][k]
__device__ __half g_wh[4*EE], g_wl[4*EE];
__device__ __half g_xf[3*MK];
__device__ __half g_of[MK];
// attention operands: q single, k hi/lo as [bh][l][64]; v single transposed [bh][d][L]
__device__ __half g_qf[BH*Ldim*HD];
__device__ __half g_kh[BH*Ldim*HD], g_kl[BH*Ldim*HD];
__device__ __half g_vth[BH*HD*Ldim];

// ============================ helpers ========================================
__device__ __forceinline__ uint32_t smem_u32(const void* p) {
    uint32_t a;
    asm("{ .reg .u64 t; cvta.to.shared.u64 t, %1; cvt.u32.u64 %0, t; }"
        : "=r"(a) : "l"(p));
    return a;
}
__device__ __forceinline__ float ex2f(float x) {
    float y; asm("ex2.approx.f32 %0, %1;" : "=f"(y) : "f"(x)); return y;
}
#define STS128(addr, r0, r1, r2, r3) \
    asm volatile("st.shared.v4.b32 [%0], {%1, %2, %3, %4};" \
                 :: "r"(addr), "r"(r0), "r"(r1), "r"(r2), "r"(r3) : "memory")

__device__ __forceinline__ void cpa16(uint32_t dst, const void* src) {
    asm volatile("cp.async.cg.shared.global [%0], [%1], 16;"
                 :: "r"(dst), "l"(src) : "memory");
}
#define CP_COMMIT() asm volatile("cp.async.commit_group;" ::: "memory")
#define CP_WAIT1()  asm volatile("cp.async.wait_group 1;" ::: "memory")
#define CP_WAIT0()  asm volatile("cp.async.wait_group 0;" ::: "memory")

__device__ __forceinline__ void ldm_x4(uint32_t* r, uint32_t addr) {
    asm volatile("ldmatrix.sync.aligned.m8n8.x4.shared.b16 {%0,%1,%2,%3}, [%4];"
                 : "=r"(r[0]), "=r"(r[1]), "=r"(r[2]), "=r"(r[3]) : "r"(addr));
}
// fp16 MMA, fp32 accumulate
__device__ __forceinline__ void mma16816(float* c, const uint32_t* a,
                                         const uint32_t* b) {
    asm volatile(
        "mma.sync.aligned.m16n8k16.row.col.f32.f16.f16.f32 "
        "{%0,%1,%2,%3}, {%4,%5,%6,%7}, {%8,%9}, {%0,%1,%2,%3};"
        : "+f"(c[0]), "+f"(c[1]), "+f"(c[2]), "+f"(c[3])
        : "r"(a[0]), "r"(a[1]), "r"(a[2]), "r"(a[3]), "r"(b[0]), "r"(b[1]));
}
// fp16 hi/lo split of a float pair (elem0 in low half)
__device__ __forceinline__ void split2h(float a, float b, uint32_t& hi, uint32_t& lo) {
    __half2 h = __floats2half2_rn(a, b);
    float2 hf = __half22float2(h);
    __half2 l = __floats2half2_rn(a - hf.x, b - hf.y);
    hi = *reinterpret_cast<uint32_t*>(&h);
    lo = *reinterpret_cast<uint32_t*>(&l);
}
__device__ __forceinline__ uint32_t pack2h(float a, float b) {
    __half2 h = __floats2half2_rn(a, b);
    return *reinterpret_cast<uint32_t*>(&h);
}

// ---------------- combined: W_eff fp16 split + x fp16 pack -------------------
#define WEFF_BLOCKS 4608            /* 4 * EE/2 / 256 */
#define XSPL_BLOCKS 18432           /* 3 * MK/4 / 256 */

__global__ void __launch_bounds__(256) weff_split_kernel(
    const float* __restrict__ inW,  const float* __restrict__ outW,
    const float* __restrict__ qd, const float* __restrict__ qu,
    const float* __restrict__ kd, const float* __restrict__ ku,
    const float* __restrict__ vd, const float* __restrict__ vu,
    const float* __restrict__ od, const float* __restrict__ ou,
    const float* __restrict__ query, const float* __restrict__ key,
    const float* __restrict__ value)
{
    int bx = blockIdx.x;
    if (bx < WEFF_BLOCKS) {
        int z = bx / (WEFF_BLOCKS / 4);
        int pidx = (bx % (WEFF_BLOCKS / 4)) * 256 + threadIdx.x;  // pair idx < EE/2
        int e = (pidx * 2) / E;
        int k = (pidx * 2) % E;
        const float* W  = (z < 3) ? (inW + z * EE) : outW;
        const float* dn = (z == 0) ? qd : (z == 1) ? kd : (z == 2) ? vd : od;
        const float* up = (z == 0) ? qu : (z == 1) ? ku : (z == 2) ? vu : ou;
        float s0 = 0.f, s1 = 0.f;
#pragma unroll
        for (int r = 0; r < 16; r++) {
            float u = up[e * 16 + r];
            s0 += u * dn[r * E + k];
            s1 += u * dn[r * E + k + 1];
        }
        float v0 = W[e * E + k] + s0;
        float v1 = W[e * E + k + 1] + s1;
        uint32_t hi, lo;
        split2h(v0, v1, hi, lo);
        ((uint32_t*)g_wh)[(size_t)z * (EE / 2) + pidx] = hi;
        ((uint32_t*)g_wl)[(size_t)z * (EE / 2) + pidx] = lo;
    } else {
        int i = bx - WEFF_BLOCKS;
        int z = i / (XSPL_BLOCKS / 3);
        size_t idx = (size_t)(i % (XSPL_BLOCKS / 3)) * 256 + threadIdx.x;  // float4 idx
        const float4* src = (const float4*)((z == 0) ? query : (z == 1) ? key : value);
        float4 v = src[idx];
        ((uint2*)g_xf)[(size_t)z * (MK / 4) + idx] =
            make_uint2(pack2h(v.x, v.y), pack2h(v.z, v.w));
    }
}

// ================= fp16 2-pass MMA GEMM ======================================
#define SKG 80                 /* smem row stride bytes (32 fp16 + pad) */
#define GA_F 0
#define GB_H 10240
#define GB_L 20480
#define GSTG 30720
#define G_SMEM (2*GSTG)        /* 61440 */
#define GKT (E/32)             /* 24 k-stages */

__device__ __forceinline__ void g_prefetch(
    uint32_t buf,
    const __half* axf, const __half* bwh, const __half* bwl,
    int m0, int e0, int k0, int tid)
{
    int row = tid >> 1, part = tid & 1;
    uint32_t ro = (uint32_t)row * SKG + (uint32_t)part * 32;
    const __half* af = axf + (size_t)(m0 + row) * E + k0 + part * 16;
    const __half* bh = bwh + (size_t)(e0 + row) * E + k0 + part * 16;
    const __half* bl = bwl + (size_t)(e0 + row) * E + k0 + part * 16;
    cpa16(buf + GA_F + ro,      af); cpa16(buf + GA_F + ro + 16, af + 8);
    cpa16(buf + GB_H + ro,      bh); cpa16(buf + GB_H + ro + 16, bh + 8);
    cpa16(buf + GB_L + ro,      bl); cpa16(buf + GB_L + ro + 16, bl + 8);
}

__global__ void __launch_bounds__(256) gemm_mma(
    const __half* __restrict__ xf,
    const __half* __restrict__ wh, const __half* __restrict__ wl,
    const float* __restrict__ bias_base,
    float* __restrict__ y0, float* __restrict__ y1, float* __restrict__ y2,
    int qz)
{
    extern __shared__ __align__(128) char smem[];
    uint32_t sb = smem_u32(smem);
    int z = blockIdx.z;
    const __half* axf = xf + (size_t)z * MK;
    const __half* bwh = wh + (size_t)z * EE;
    const __half* bwl = wl + (size_t)z * EE;
    float* y = (z == 0) ? y0 : (z == 1) ? y1 : y2;
    const float* bias = bias_base + z * E;
    int m0 = blockIdx.y * 128, e0 = blockIdx.x * 128;
    int tid = threadIdx.x, wid = tid >> 5, lane = tid & 31;
    int wm = wid & 1, wn = wid >> 1;

    uint32_t arow = (uint32_t)(wm * 64 + (lane & 15)) * SKG + (uint32_t)(lane >> 4) * 16;
    uint32_t brow = (uint32_t)(wn * 32 + (lane >> 4) * 8 + (lane & 7)) * SKG
                  + (uint32_t)((lane >> 3) & 1) * 16;

    float acc[4][4][4];
#pragma unroll
    for (int a = 0; a < 4; a++)
#pragma unroll
        for (int b = 0; b < 4; b++)
#pragma unroll
            for (int c = 0; c < 4; c++) acc[a][b][c] = 0.f;

    g_prefetch(sb, axf, bwh, bwl, m0, e0, 0, tid);
    CP_COMMIT();

    for (int kt = 0; kt < GKT; kt++) {
        uint32_t cb = sb + (uint32_t)(kt & 1) * GSTG;
        if (kt + 1 < GKT) {
            g_prefetch(sb + (uint32_t)((kt + 1) & 1) * GSTG,
                       axf, bwh, bwl, m0, e0, (kt + 1) * 32, tid);
            CP_COMMIT();
            CP_WAIT1();
        } else {
            CP_WAIT0();
        }
        __syncthreads();
#pragma unroll
        for (int ks = 0; ks < 2; ks++) {
            uint32_t koff = (uint32_t)ks * 32;
            uint32_t bhf[2][4], blf[2][4];
            ldm_x4(bhf[0], cb + GB_H + brow + koff);
            ldm_x4(bhf[1], cb + GB_H + brow + 16 * SKG + koff);
            ldm_x4(blf[0], cb + GB_L + brow + koff);
            ldm_x4(blf[1], cb + GB_L + brow + 16 * SKG + koff);
#pragma unroll
            for (int mi = 0; mi < 4; mi++) {
                uint32_t af[4];
                ldm_x4(af, cb + GA_F + arow + mi * 16 * SKG + koff);
#pragma unroll
                for (int ni = 0; ni < 4; ni++) {
                    const uint32_t* bfh = bhf[ni >> 1] + (ni & 1) * 2;
                    const uint32_t* bfl = blf[ni >> 1] + (ni & 1) * 2;
                    mma16816(acc[mi][ni], af, bfh);
                    mma16816(acc[mi][ni], af, bfl);
                }
            }
        }
        __syncthreads();
    }

    float qs = (z == qz) ? 0.125f * 1.4426950408889634f : 1.0f;
    int r = lane >> 2, cp = (lane & 3) * 2;
#pragma unroll
    for (int mi = 0; mi < 4; mi++) {
        int row0 = m0 + wm * 64 + mi * 16 + r;
#pragma unroll
        for (int ni = 0; ni < 4; ni++) {
            int col = e0 + wn * 32 + ni * 8 + cp;
            float b0 = bias[col], b1 = bias[col + 1];
            float2 v0 = make_float2((acc[mi][ni][0] + b0) * qs,
                                    (acc[mi][ni][1] + b1) * qs);
            float2 v1 = make_float2((acc[mi][ni][2] + b0) * qs,
                                    (acc[mi][ni][3] + b1) * qs);
            *(float2*)(y + (size_t)row0 * E + col) = v0;
            *(float2*)(y + (size_t)(row0 + 8) * E + col) = v1;
        }
    }
}

// ---------------- combined prep: q pack / k split + v transpose (single) -----
#define QK_BLOCKS 12288   /* 2 * MK/4/256 */
#define PREP_BLOCKS (QK_BLOCKS + (Ldim/64)*BH)

__global__ void __launch_bounds__(256) prep_kernel()
{
    int bx = blockIdx.x;
    if (bx < QK_BLOCKS) {
        int z = bx / (QK_BLOCKS / 2);
        size_t idx = (size_t)(bx % (QK_BLOCKS / 2)) * 256 + threadIdx.x;
        const float4* src = (const float4*)(z ? g_k : g_q);
        float4 v = src[idx];
        int e4 = (int)(idx % (E / 4));
        int ln = (int)(idx / (E / 4));          // l*Nb + nb
        int e = e4 * 4, h = e >> 6, d = e & 63;
        int l = ln >> 2, nb = ln & 3;
        size_t dst = ((size_t)(nb * H + h) * Ldim + l) * HD + d;
        if (z == 0) {
            *(uint2*)(g_qf + dst) = make_uint2(pack2h(v.x, v.y), pack2h(v.z, v.w));
        } else {
            uint32_t h0, l0, h1, l1;
            split2h(v.x, v.y, h0, l0);
            split2h(v.z, v.w, h1, l1);
            *(uint2*)(g_kh + dst) = make_uint2(h0, h1);
            *(uint2*)(g_kl + dst) = make_uint2(l0, l1);
        }
    } else {
        __shared__ float vt[64][65];
        int i = bx - QK_BLOCKS;
        int s0 = (i & 31) * 64;
        int bh = i >> 5;
        int nb = bh / H, h = bh % H;
        int t = threadIdx.x;
        {
            int s = t >> 2, dq = (t & 3) * 16;
            const float* src = g_v + ((size_t)(s0 + s) * Nb + nb) * E + h * HD + dq;
#pragma unroll
            for (int j = 0; j < 4; j++) {
                float4 v = *(const float4*)(src + j * 4);
                vt[s][dq + j * 4 + 0] = v.x;
                vt[s][dq + j * 4 + 1] = v.y;
                vt[s][dq + j * 4 + 2] = v.z;
                vt[s][dq + j * 4 + 3] = v.w;
            }
        }
        __syncthreads();
        {
            int d = t >> 2, sq = (t & 3) * 16;
            uint32_t hw[8];
#pragma unroll
            for (int j = 0; j < 8; j++)
                hw[j] = pack2h(vt[sq + 2 * j][d], vt[sq + 2 * j + 1][d]);
            size_t dst = ((size_t)bh * HD + d) * Ldim + s0 + sq;
            ((uint4*)(g_vth + dst))[0] = make_uint4(hw[0], hw[1], hw[2], hw[3]);
            ((uint4*)(g_vth + dst))[1] = make_uint4(hw[4], hw[5], hw[6], hw[7]);
        }
    }
}

// ================= warp-MMA flash attention (fp16, V single) =================
// grid (L/64, BH), 128 threads, 4 CTAs/SM target.
// QK: qf*(kh+kl) 2-pass. PV: P-rounded-fp16 * v-single, exact-l norm.
#define SKB 144
#define STAGE_B 27648          /* KH 9216 + KL 9216 + VH 9216 */
#define KH_O 0
#define KL_O 9216
#define VH_O 18432
#define S_TOTAL3 (2*STAGE_B)   /* 55296 */
#define NT (Ldim / 64)

__device__ __forceinline__ void kv_prefetch(uint32_t buf, int bh, int s0, int tid)
{
    int m = tid >> 1;
    int hf = tid & 1;
    uint32_t ro = (uint32_t)m * SKB + (uint32_t)hf * 64;
    const __half* kh = g_kh + ((size_t)bh * Ldim + s0 + m) * HD + hf * 32;
    const __half* kl = g_kl + ((size_t)bh * Ldim + s0 + m) * HD + hf * 32;
    const __half* vh = g_vth + ((size_t)bh * HD + m) * Ldim + s0 + hf * 32;
#pragma unroll
    for (int c = 0; c < 4; c++) {
        cpa16(buf + KH_O + ro + c * 16, kh + c * 8);
        cpa16(buf + KL_O + ro + c * 16, kl + c * 8);
        cpa16(buf + VH_O + ro + c * 16, vh + c * 8);
    }
}

__global__ void __launch_bounds__(128, 4) attn_mma3()
{
    extern __shared__ __align__(128) char smem[];
    uint32_t sb = smem_u32(smem);
    int tid = threadIdx.x;
    int wid = tid >> 5, lane = tid & 31;
    int bh = blockIdx.y;
    int nb = bh / H, h = bh % H;
    int q0 = blockIdx.x * 64;

    // stage-0 KV prefetch (buffer 0)
    kv_prefetch(sb, bh, 0, tid);
    CP_COMMIT();

    // stage Q (single fp16) through stage-1 buffer
    {
        uint32_t q_s = sb + STAGE_B;
        int m = tid >> 1;
        int u0 = (tid & 1) * 4;
        uint32_t o = (uint32_t)m * SKB + (uint32_t)u0 * 16;
        const uint4* s = (const uint4*)(g_qf + ((size_t)bh * Ldim + q0 + m) * HD) + u0;
        uint4 a = s[0], b = s[1], c = s[2], d = s[3];
        STS128(q_s + o,      a.x, a.y, a.z, a.w);
        STS128(q_s + o + 16, b.x, b.y, b.z, b.w);
        STS128(q_s + o + 32, c.x, c.y, c.z, c.w);
        STS128(q_s + o + 48, d.x, d.y, d.z, d.w);
    }
    __syncthreads();

    uint32_t qrow = (uint32_t)(16 * wid + (lane & 15)) * SKB + (uint32_t)(lane >> 4) * 16;
    uint32_t brow = (uint32_t)(((lane >> 4) * 8 + (lane & 7))) * SKB
                  + (uint32_t)((lane >> 3) & 1) * 16;

    // Q fragments -> registers
    uint32_t qf[4][4];
#pragma unroll
    for (int k = 0; k < 4; k++)
        ldm_x4(qf[k], sb + STAGE_B + qrow + k * 32);
    __syncthreads();   // all warps done with Q before stage-1 prefetch

    float Oa[8][4];
#pragma unroll
    for (int n = 0; n < 8; n++)
#pragma unroll
        for (int j = 0; j < 4; j++) Oa[n][j] = 0.f;
    float m_lo = -INFINITY, m_hi = -INFINITY, l_lo = 0.f, l_hi = 0.f;

    for (int t = 0; t < NT; t++) {
        uint32_t cb = sb + (uint32_t)(t & 1) * STAGE_B;
        if (t + 1 < NT) {
            kv_prefetch(sb + (uint32_t)((t + 1) & 1) * STAGE_B,
                        bh, (t + 1) * 64, tid);
            CP_COMMIT();
            CP_WAIT1();
        } else {
            CP_WAIT0();
        }
        __syncthreads();

        // ---- S = Q (Kh + Kl)^T : 2-pass --------------------------------------
        float c[8][4];
#pragma unroll
        for (int n = 0; n < 8; n++)
#pragma unroll
            for (int j = 0; j < 4; j++) c[n][j] = 0.f;
#pragma unroll
        for (int np = 0; np < 4; np++) {
            uint32_t baseH = cb + KH_O + brow + np * (16 * SKB);
            uint32_t baseL = cb + KL_O + brow + np * (16 * SKB);
#pragma unroll
            for (int k = 0; k < 4; k++) {
                uint32_t bhh[4], bll[4];
                ldm_x4(bhh, baseH + k * 32);
                ldm_x4(bll, baseL + k * 32);
                mma16816(c[2 * np],     qf[k], bhh);
                mma16816(c[2 * np],     qf[k], bll);
                mma16816(c[2 * np + 1], qf[k], bhh + 2);
                mma16816(c[2 * np + 1], qf[k], bll + 2);
            }
        }

        // ---- online softmax (quad-local rows) -------------------------------
        float mn_lo = m_lo, mn_hi = m_hi;
#pragma unroll
        for (int n = 0; n < 8; n++) {
            mn_lo = fmaxf(mn_lo, fmaxf(c[n][0], c[n][1]));
            mn_hi = fmaxf(mn_hi, fmaxf(c[n][2], c[n][3]));
        }
        mn_lo = fmaxf(mn_lo, __shfl_xor_sync(0xffffffffu, mn_lo, 1));
        mn_lo = fmaxf(mn_lo, __shfl_xor_sync(0xffffffffu, mn_lo, 2));
        mn_hi = fmaxf(mn_hi, __shfl_xor_sync(0xffffffffu, mn_hi, 1));
        mn_hi = fmaxf(mn_hi, __shfl_xor_sync(0xffffffffu, mn_hi, 2));
        float corr_lo = ex2f(m_lo - mn_lo);
        float corr_hi = ex2f(m_hi - mn_hi);
        m_lo = mn_lo; m_hi = mn_hi;
        l_lo *= corr_lo; l_hi *= corr_hi;
#pragma unroll
        for (int n = 0; n < 8; n++) {
            Oa[n][0] *= corr_lo; Oa[n][1] *= corr_lo;
            Oa[n][2] *= corr_hi; Oa[n][3] *= corr_hi;
        }
        // exp -> round to fp16 P; accumulate l from ROUNDED values (exact norm)
        uint32_t ph[4][4];
#pragma unroll
        for (int n = 0; n < 8; n++) {
            float p0 = ex2f(c[n][0] - mn_lo);
            float p1 = ex2f(c[n][1] - mn_lo);
            float p2 = ex2f(c[n][2] - mn_hi);
            float p3 = ex2f(c[n][3] - mn_hi);
            __half2 h01 = __floats2half2_rn(p0, p1);
            __half2 h23 = __floats2half2_rn(p2, p3);
            float2 f01 = __half22float2(h01);
            float2 f23 = __half22float2(h23);
            l_lo += f01.x + f01.y;
            l_hi += f23.x + f23.y;
            int kc = n >> 1, o = (n & 1) * 2;
            ph[kc][o]     = *reinterpret_cast<uint32_t*>(&h01);
            ph[kc][o + 1] = *reinterpret_cast<uint32_t*>(&h23);
        }

        // ---- O += P V (single-V) ---------------------------------------------
#pragma unroll
        for (int np = 0; np < 4; np++) {
            uint32_t baseH = cb + VH_O + brow + np * (16 * SKB);
#pragma unroll
            for (int k = 0; k < 4; k++) {
                uint32_t vhh[4];
                ldm_x4(vhh, baseH + k * 32);
                mma16816(Oa[2 * np],     ph[k], vhh);
                mma16816(Oa[2 * np + 1], ph[k], vhh + 2);
            }
        }
        __syncthreads();
    }

    // ---- epilogue: normalize + fp16 pack write -------------------------------
    l_lo += __shfl_xor_sync(0xffffffffu, l_lo, 1);
    l_lo += __shfl_xor_sync(0xffffffffu, l_lo, 2);
    l_hi += __shfl_xor_sync(0xffffffffu, l_hi, 1);
    l_hi += __shfl_xor_sync(0xffffffffu, l_hi, 2);
    float inv_lo = 1.f / l_lo, inv_hi = 1.f / l_hi;

    int r = lane >> 2, cc = (lane & 3) * 2;
    size_t base_lo = ((size_t)(q0 + 16 * wid + r) * Nb + nb) * E + h * HD;
    size_t base_hi = ((size_t)(q0 + 16 * wid + r + 8) * Nb + nb) * E + h * HD;
#pragma unroll
    for (int n = 0; n < 8; n++) {
        int d = n * 8 + cc;
        ((uint32_t*)g_of)[(base_lo + d) >> 1] =
            pack2h(Oa[n][0] * inv_lo, Oa[n][1] * inv_lo);
        ((uint32_t*)g_of)[(base_hi + d) >> 1] =
            pack2h(Oa[n][2] * inv_hi, Oa[n][3] * inv_hi);
    }
}

// ---------------- launcher ---------------------------------------------------
extern "C" void kernel_launch(void* const* d_in, const int* in_sizes, int n_in,
                              void* d_out, int out_size)
{
    const float* query = (const float*)d_in[0];
    const float* key   = (const float*)d_in[1];
    const float* value = (const float*)d_in[2];
    const float* in_w  = (const float*)d_in[3];
    const float* in_b  = (const float*)d_in[4];
    const float* q_dn  = (const float*)d_in[5];
    const float* q_up  = (const float*)d_in[6];
    const float* k_dn  = (const float*)d_in[7];
    const float* k_up  = (const float*)d_in[8];
    const float* v_dn  = (const float*)d_in[9];
    const float* v_up  = (const float*)d_in[10];
    const float* out_w = (const float*)d_in[11];
    const float* out_b = (const float*)d_in[12];
    const float* o_dn  = (const float*)d_in[13];
    const float* o_up  = (const float*)d_in[14];

    float *p_q, *p_k, *p_v;
    __half *p_wh, *p_wl, *p_xf, *p_of;
    cudaGetSymbolAddress((void**)&p_q, g_q);
    cudaGetSymbolAddress((void**)&p_k, g_k);
    cudaGetSymbolAddress((void**)&p_v, g_v);
    cudaGetSymbolAddress((void**)&p_wh, g_wh);
    cudaGetSymbolAddress((void**)&p_wl, g_wl);
    cudaGetSymbolAddress((void**)&p_xf, g_xf);
    cudaGetSymbolAddress((void**)&p_of, g_of);

    cudaFuncSetAttribute(attn_mma3,
                         cudaFuncAttributeMaxDynamicSharedMemorySize, S_TOTAL3);
    cudaFuncSetAttribute(gemm_mma,
                         cudaFuncAttributeMaxDynamicSharedMemorySize, G_SMEM);

    // 1) W_eff -> fp16 hi/lo + input fp16 pack
    weff_split_kernel<<<WEFF_BLOCKS + XSPL_BLOCKS, 256>>>(
        in_w, out_w, q_dn, q_up, k_dn, k_up, v_dn, v_up, o_dn, o_up,
        query, key, value);
    // 2) QKV projections via fp16 2-pass MMA (q pre-scaled by 0.125*log2e)
    gemm_mma<<<dim3(E / 128, Mrows / 128, 3), 256, G_SMEM>>>(
        p_xf, p_wh, p_wl, in_b, p_q, p_k, p_v, /*qz=*/0);
    // 3) combined prep: q fp16 pack / k fp16 split + v transpose (single fp16)
    prep_kernel<<<PREP_BLOCKS, 256>>>();
    // 4) warp-MMA flash attention (launch #4 -> profiled); writes g_of
    attn_mma3<<<dim3(Ldim / 64, BH), 128, S_TOTAL3>>>();
    // 5) output projection via fp16 2-pass MMA -> d_out
    gemm_mma<<<dim3(E / 128, Mrows / 128, 1), 256, G_SMEM>>>(
        p_of, p_wh + 3 * (size_t)EE, p_wl + 3 * (size_t)EE, out_b,
        (float*)d_out, (float*)d_out, (float*)d_out, /*qz=*/-1);
}

// round 12
// speedup vs baseline: 1.6278x; 1.0131x over previous
#include <cuda_runtime.h>
#include <cuda_fp16.h>
#include <math.h>
#include <stdint.h>

#define Ldim 2048
#define Nb   4
#define E    768
#define H    12
#define HD   64
#define BH   (Nb*H)         /* 48 */
#define Mrows (Ldim*Nb)     /* 8192 */
#define EE   (E*E)          /* 589824 */
#define MK   (Mrows*E)      /* 6291456 */

// ---------------- scratch (static device globals; no runtime allocation) ----
__device__ float g_v[MK];
// fp16 operands: weights hi/lo [z][e][k]; activations single [z][m][k]
__device__ __half g_wh[4*EE], g_wl[4*EE];
__device__ __half g_xf[3*MK];
__device__ __half g_of[MK];
// attention operands: q single, k hi/lo as [bh][l][64]; v single transposed [bh][d][L]
__device__ __half g_qf[BH*Ldim*HD];
__device__ __half g_kh[BH*Ldim*HD], g_kl[BH*Ldim*HD];
__device__ __half g_vth[BH*HD*Ldim];

// ============================ helpers ========================================
__device__ __forceinline__ uint32_t smem_u32(const void* p) {
    uint32_t a;
    asm("{ .reg .u64 t; cvta.to.shared.u64 t, %1; cvt.u32.u64 %0, t; }"
        : "=r"(a) : "l"(p));
    return a;
}
__device__ __forceinline__ float ex2f(float x) {
    float y; asm("ex2.approx.f32 %0, %1;" : "=f"(y) : "f"(x)); return y;
}
#define STS128(addr, r0, r1, r2, r3) \
    asm volatile("st.shared.v4.b32 [%0], {%1, %2, %3, %4};" \
                 :: "r"(addr), "r"(r0), "r"(r1), "r"(r2), "r"(r3) : "memory")

__device__ __forceinline__ void cpa16(uint32_t dst, const void* src) {
    asm volatile("cp.async.cg.shared.global [%0], [%1], 16;"
                 :: "r"(dst), "l"(src) : "memory");
}
#define CP_COMMIT() asm volatile("cp.async.commit_group;" ::: "memory")
#define CP_WAIT1()  asm volatile("cp.async.wait_group 1;" ::: "memory")
#define CP_WAIT0()  asm volatile("cp.async.wait_group 0;" ::: "memory")

__device__ __forceinline__ void ldm_x4(uint32_t* r, uint32_t addr) {
    asm volatile("ldmatrix.sync.aligned.m8n8.x4.shared.b16 {%0,%1,%2,%3}, [%4];"
                 : "=r"(r[0]), "=r"(r[1]), "=r"(r[2]), "=r"(r[3]) : "r"(addr));
}
// fp16 MMA, fp32 accumulate
__device__ __forceinline__ void mma16816(float* c, const uint32_t* a,
                                         const uint32_t* b) {
    asm volatile(
        "mma.sync.aligned.m16n8k16.row.col.f32.f16.f16.f32 "
        "{%0,%1,%2,%3}, {%4,%5,%6,%7}, {%8,%9}, {%0,%1,%2,%3};"
        : "+f"(c[0]), "+f"(c[1]), "+f"(c[2]), "+f"(c[3])
        : "r"(a[0]), "r"(a[1]), "r"(a[2]), "r"(a[3]), "r"(b[0]), "r"(b[1]));
}
// fp16 hi/lo split of a float pair (elem0 in low half)
__device__ __forceinline__ void split2h(float a, float b, uint32_t& hi, uint32_t& lo) {
    __half2 h = __floats2half2_rn(a, b);
    float2 hf = __half22float2(h);
    __half2 l = __floats2half2_rn(a - hf.x, b - hf.y);
    hi = *reinterpret_cast<uint32_t*>(&h);
    lo = *reinterpret_cast<uint32_t*>(&l);
}
__device__ __forceinline__ uint32_t pack2h(float a, float b) {
    __half2 h = __floats2half2_rn(a, b);
    return *reinterpret_cast<uint32_t*>(&h);
}

// ---------------- combined: W_eff fp16 split + x fp16 pack -------------------
#define WEFF_BLOCKS 4608            /* 4 * EE/2 / 256 */
#define XSPL_BLOCKS 18432           /* 3 * MK/4 / 256 */

__global__ void __launch_bounds__(256) weff_split_kernel(
    const float* __restrict__ inW,  const float* __restrict__ outW,
    const float* __restrict__ qd, const float* __restrict__ qu,
    const float* __restrict__ kd, const float* __restrict__ ku,
    const float* __restrict__ vd, const float* __restrict__ vu,
    const float* __restrict__ od, const float* __restrict__ ou,
    const float* __restrict__ query, const float* __restrict__ key,
    const float* __restrict__ value)
{
    int bx = blockIdx.x;
    if (bx < WEFF_BLOCKS) {
        int z = bx / (WEFF_BLOCKS / 4);
        int pidx = (bx % (WEFF_BLOCKS / 4)) * 256 + threadIdx.x;  // pair idx < EE/2
        int e = (pidx * 2) / E;
        int k = (pidx * 2) % E;
        const float* W  = (z < 3) ? (inW + z * EE) : outW;
        const float* dn = (z == 0) ? qd : (z == 1) ? kd : (z == 2) ? vd : od;
        const float* up = (z == 0) ? qu : (z == 1) ? ku : (z == 2) ? vu : ou;
        float s0 = 0.f, s1 = 0.f;
#pragma unroll
        for (int r = 0; r < 16; r++) {
            float u = up[e * 16 + r];
            s0 += u * dn[r * E + k];
            s1 += u * dn[r * E + k + 1];
        }
        float v0 = W[e * E + k] + s0;
        float v1 = W[e * E + k + 1] + s1;
        uint32_t hi, lo;
        split2h(v0, v1, hi, lo);
        ((uint32_t*)g_wh)[(size_t)z * (EE / 2) + pidx] = hi;
        ((uint32_t*)g_wl)[(size_t)z * (EE / 2) + pidx] = lo;
    } else {
        int i = bx - WEFF_BLOCKS;
        int z = i / (XSPL_BLOCKS / 3);
        size_t idx = (size_t)(i % (XSPL_BLOCKS / 3)) * 256 + threadIdx.x;  // float4 idx
        const float4* src = (const float4*)((z == 0) ? query : (z == 1) ? key : value);
        float4 v = src[idx];
        ((uint2*)g_xf)[(size_t)z * (MK / 4) + idx] =
            make_uint2(pack2h(v.x, v.y), pack2h(v.z, v.w));
    }
}

// ================= fp16 2-pass MMA GEMM ======================================
// mode 0: write fp32 y.   mode 1 (QKV): z=0 -> g_qf fp16 pack [bh][l][64],
// z=1 -> g_kh/g_kl fp16 split [bh][l][64], z=2 -> fp32 g_v.
#define SKG 80                 /* smem row stride bytes (32 fp16 + pad) */
#define GA_F 0
#define GB_H 10240
#define GB_L 20480
#define GSTG 30720
#define G_SMEM (2*GSTG)        /* 61440 */
#define GKT (E/32)             /* 24 k-stages */

__device__ __forceinline__ void g_prefetch(
    uint32_t buf,
    const __half* axf, const __half* bwh, const __half* bwl,
    int m0, int e0, int k0, int tid)
{
    int row = tid >> 1, part = tid & 1;
    uint32_t ro = (uint32_t)row * SKG + (uint32_t)part * 32;
    const __half* af = axf + (size_t)(m0 + row) * E + k0 + part * 16;
    const __half* bh = bwh + (size_t)(e0 + row) * E + k0 + part * 16;
    const __half* bl = bwl + (size_t)(e0 + row) * E + k0 + part * 16;
    cpa16(buf + GA_F + ro,      af); cpa16(buf + GA_F + ro + 16, af + 8);
    cpa16(buf + GB_H + ro,      bh); cpa16(buf + GB_H + ro + 16, bh + 8);
    cpa16(buf + GB_L + ro,      bl); cpa16(buf + GB_L + ro + 16, bl + 8);
}

__global__ void __launch_bounds__(256, 2) gemm_mma(
    const __half* __restrict__ xf,
    const __half* __restrict__ wh, const __half* __restrict__ wl,
    const float* __restrict__ bias_base,
    float* __restrict__ yout,
    int mode)
{
    extern __shared__ __align__(128) char smem[];
    uint32_t sb = smem_u32(smem);
    int z = blockIdx.z;
    const __half* axf = xf + (size_t)z * MK;
    const __half* bwh = wh + (size_t)z * EE;
    const __half* bwl = wl + (size_t)z * EE;
    const float* bias = bias_base + z * E;
    int m0 = blockIdx.y * 128, e0 = blockIdx.x * 128;
    int tid = threadIdx.x, wid = tid >> 5, lane = tid & 31;
    int wm = wid & 1, wn = wid >> 1;

    uint32_t arow = (uint32_t)(wm * 64 + (lane & 15)) * SKG + (uint32_t)(lane >> 4) * 16;
    uint32_t brow = (uint32_t)(wn * 32 + (lane >> 4) * 8 + (lane & 7)) * SKG
                  + (uint32_t)((lane >> 3) & 1) * 16;

    float acc[4][4][4];
#pragma unroll
    for (int a = 0; a < 4; a++)
#pragma unroll
        for (int b = 0; b < 4; b++)
#pragma unroll
            for (int c = 0; c < 4; c++) acc[a][b][c] = 0.f;

    g_prefetch(sb, axf, bwh, bwl, m0, e0, 0, tid);
    CP_COMMIT();

    for (int kt = 0; kt < GKT; kt++) {
        uint32_t cb = sb + (uint32_t)(kt & 1) * GSTG;
        if (kt + 1 < GKT) {
            g_prefetch(sb + (uint32_t)((kt + 1) & 1) * GSTG,
                       axf, bwh, bwl, m0, e0, (kt + 1) * 32, tid);
            CP_COMMIT();
            CP_WAIT1();
        } else {
            CP_WAIT0();
        }
        __syncthreads();
#pragma unroll
        for (int ks = 0; ks < 2; ks++) {
            uint32_t koff = (uint32_t)ks * 32;
            uint32_t bhf[2][4], blf[2][4];
            ldm_x4(bhf[0], cb + GB_H + brow + koff);
            ldm_x4(bhf[1], cb + GB_H + brow + 16 * SKG + koff);
            ldm_x4(blf[0], cb + GB_L + brow + koff);
            ldm_x4(blf[1], cb + GB_L + brow + 16 * SKG + koff);
#pragma unroll
            for (int mi = 0; mi < 4; mi++) {
                uint32_t af[4];
                ldm_x4(af, cb + GA_F + arow + mi * 16 * SKG + koff);
#pragma unroll
                for (int ni = 0; ni < 4; ni++) {
                    const uint32_t* bfh = bhf[ni >> 1] + (ni & 1) * 2;
                    const uint32_t* bfl = blf[ni >> 1] + (ni & 1) * 2;
                    mma16816(acc[mi][ni], af, bfh);
                    mma16816(acc[mi][ni], af, bfl);
                }
            }
        }
        __syncthreads();
    }

    int r = lane >> 2, cp = (lane & 3) * 2;
    if (mode == 1 && z < 2) {
        // fused attention-format epilogue: [bh][l][64] fp16
        float qs = (z == 0) ? 0.125f * 1.4426950408889634f : 1.0f;
#pragma unroll
        for (int mi = 0; mi < 4; mi++) {
#pragma unroll
            for (int ni = 0; ni < 4; ni++) {
                int col = e0 + wn * 32 + ni * 8 + cp;
                int hh = col >> 6, d = col & 63;
                float b0 = bias[col], b1 = bias[col + 1];
#pragma unroll
                for (int rr = 0; rr < 2; rr++) {
                    int row = m0 + wm * 64 + mi * 16 + r + rr * 8;
                    int l = row >> 2, nb = row & 3;
                    size_t w = ((((size_t)(nb * H + hh) * Ldim + l) * HD) + d) >> 1;
                    float a = (acc[mi][ni][2 * rr]     + b0) * qs;
                    float b = (acc[mi][ni][2 * rr + 1] + b1) * qs;
                    if (z == 0) {
                        ((uint32_t*)g_qf)[w] = pack2h(a, b);
                    } else {
                        uint32_t hi, lo;
                        split2h(a, b, hi, lo);
                        ((uint32_t*)g_kh)[w] = hi;
                        ((uint32_t*)g_kl)[w] = lo;
                    }
                }
            }
        }
    } else {
        float* y = (mode == 1) ? g_v : yout;
#pragma unroll
        for (int mi = 0; mi < 4; mi++) {
            int row0 = m0 + wm * 64 + mi * 16 + r;
#pragma unroll
            for (int ni = 0; ni < 4; ni++) {
                int col = e0 + wn * 32 + ni * 8 + cp;
                float b0 = bias[col], b1 = bias[col + 1];
                float2 v0 = make_float2(acc[mi][ni][0] + b0, acc[mi][ni][1] + b1);
                float2 v1 = make_float2(acc[mi][ni][2] + b0, acc[mi][ni][3] + b1);
                *(float2*)(y + (size_t)row0 * E + col) = v0;
                *(float2*)(y + (size_t)(row0 + 8) * E + col) = v1;
            }
        }
    }
}

// ---------------- prep: v -> transposed fp16 [bh][d][L] ----------------------
__global__ void __launch_bounds__(256) v_prep()
{
    __shared__ float vt[64][65];
    int bh = blockIdx.y;
    int s0 = blockIdx.x * 64;
    int nb = bh / H, h = bh % H;
    int t = threadIdx.x;
    {
        int s = t >> 2, dq = (t & 3) * 16;
        const float* src = g_v + ((size_t)(s0 + s) * Nb + nb) * E + h * HD + dq;
#pragma unroll
        for (int j = 0; j < 4; j++) {
            float4 v = *(const float4*)(src + j * 4);
            vt[s][dq + j * 4 + 0] = v.x;
            vt[s][dq + j * 4 + 1] = v.y;
            vt[s][dq + j * 4 + 2] = v.z;
            vt[s][dq + j * 4 + 3] = v.w;
        }
    }
    __syncthreads();
    {
        int d = t >> 2, sq = (t & 3) * 16;
        uint32_t hw[8];
#pragma unroll
        for (int j = 0; j < 8; j++)
            hw[j] = pack2h(vt[sq + 2 * j][d], vt[sq + 2 * j + 1][d]);
        size_t dst = ((size_t)bh * HD + d) * Ldim + s0 + sq;
        ((uint4*)(g_vth + dst))[0] = make_uint4(hw[0], hw[1], hw[2], hw[3]);
        ((uint4*)(g_vth + dst))[1] = make_uint4(hw[4], hw[5], hw[6], hw[7]);
    }
}

// ================= warp-MMA flash attention (fp16, V single) =================
#define SKB 144
#define STAGE_B 27648          /* KH 9216 + KL 9216 + VH 9216 */
#define KH_O 0
#define KL_O 9216
#define VH_O 18432
#define S_TOTAL3 (2*STAGE_B)   /* 55296 */
#define NT (Ldim / 64)

__device__ __forceinline__ void kv_prefetch(uint32_t buf, int bh, int s0, int tid)
{
    int m = tid >> 1;
    int hf = tid & 1;
    uint32_t ro = (uint32_t)m * SKB + (uint32_t)hf * 64;
    const __half* kh = g_kh + ((size_t)bh * Ldim + s0 + m) * HD + hf * 32;
    const __half* kl = g_kl + ((size_t)bh * Ldim + s0 + m) * HD + hf * 32;
    const __half* vh = g_vth + ((size_t)bh * HD + m) * Ldim + s0 + hf * 32;
#pragma unroll
    for (int c = 0; c < 4; c++) {
        cpa16(buf + KH_O + ro + c * 16, kh + c * 8);
        cpa16(buf + KL_O + ro + c * 16, kl + c * 8);
        cpa16(buf + VH_O + ro + c * 16, vh + c * 8);
    }
}

__global__ void __launch_bounds__(128, 4) attn_mma3()
{
    extern __shared__ __align__(128) char smem[];
    uint32_t sb = smem_u32(smem);
    int tid = threadIdx.x;
    int wid = tid >> 5, lane = tid & 31;
    int bh = blockIdx.y;
    int nb = bh / H, h = bh % H;
    int q0 = blockIdx.x * 64;

    kv_prefetch(sb, bh, 0, tid);
    CP_COMMIT();

    {
        uint32_t q_s = sb + STAGE_B;
        int m = tid >> 1;
        int u0 = (tid & 1) * 4;
        uint32_t o = (uint32_t)m * SKB + (uint32_t)u0 * 16;
        const uint4* s = (const uint4*)(g_qf + ((size_t)bh * Ldim + q0 + m) * HD) + u0;
        uint4 a = s[0], b = s[1], c = s[2], d = s[3];
        STS128(q_s + o,      a.x, a.y, a.z, a.w);
        STS128(q_s + o + 16, b.x, b.y, b.z, b.w);
        STS128(q_s + o + 32, c.x, c.y, c.z, c.w);
        STS128(q_s + o + 48, d.x, d.y, d.z, d.w);
    }
    __syncthreads();

    uint32_t qrow = (uint32_t)(16 * wid + (lane & 15)) * SKB + (uint32_t)(lane >> 4) * 16;
    uint32_t brow = (uint32_t)(((lane >> 4) * 8 + (lane & 7))) * SKB
                  + (uint32_t)((lane >> 3) & 1) * 16;

    uint32_t qf[4][4];
#pragma unroll
    for (int k = 0; k < 4; k++)
        ldm_x4(qf[k], sb + STAGE_B + qrow + k * 32);
    __syncthreads();

    float Oa[8][4];
#pragma unroll
    for (int n = 0; n < 8; n++)
#pragma unroll
        for (int j = 0; j < 4; j++) Oa[n][j] = 0.f;
    float m_lo = -INFINITY, m_hi = -INFINITY, l_lo = 0.f, l_hi = 0.f;

    for (int t = 0; t < NT; t++) {
        uint32_t cb = sb + (uint32_t)(t & 1) * STAGE_B;
        if (t + 1 < NT) {
            kv_prefetch(sb + (uint32_t)((t + 1) & 1) * STAGE_B,
                        bh, (t + 1) * 64, tid);
            CP_COMMIT();
            CP_WAIT1();
        } else {
            CP_WAIT0();
        }
        __syncthreads();

        // ---- S = Q (Kh + Kl)^T : 2-pass --------------------------------------
        float c[8][4];
#pragma unroll
        for (int n = 0; n < 8; n++)
#pragma unroll
            for (int j = 0; j < 4; j++) c[n][j] = 0.f;
#pragma unroll
        for (int np = 0; np < 4; np++) {
            uint32_t baseH = cb + KH_O + brow + np * (16 * SKB);
            uint32_t baseL = cb + KL_O + brow + np * (16 * SKB);
#pragma unroll
            for (int k = 0; k < 4; k++) {
                uint32_t bhh[4], bll[4];
                ldm_x4(bhh, baseH + k * 32);
                ldm_x4(bll, baseL + k * 32);
                mma16816(c[2 * np],     qf[k], bhh);
                mma16816(c[2 * np],     qf[k], bll);
                mma16816(c[2 * np + 1], qf[k], bhh + 2);
                mma16816(c[2 * np + 1], qf[k], bll + 2);
            }
        }

        // ---- online softmax (quad-local rows) -------------------------------
        float mn_lo = m_lo, mn_hi = m_hi;
#pragma unroll
        for (int n = 0; n < 8; n++) {
            mn_lo = fmaxf(mn_lo, fmaxf(c[n][0], c[n][1]));
            mn_hi = fmaxf(mn_hi, fmaxf(c[n][2], c[n][3]));
        }
        mn_lo = fmaxf(mn_lo, __shfl_xor_sync(0xffffffffu, mn_lo, 1));
        mn_lo = fmaxf(mn_lo, __shfl_xor_sync(0xffffffffu, mn_lo, 2));
        mn_hi = fmaxf(mn_hi, __shfl_xor_sync(0xffffffffu, mn_hi, 1));
        mn_hi = fmaxf(mn_hi, __shfl_xor_sync(0xffffffffu, mn_hi, 2));
        float corr_lo = ex2f(m_lo - mn_lo);
        float corr_hi = ex2f(m_hi - mn_hi);
        m_lo = mn_lo; m_hi = mn_hi;
        l_lo *= corr_lo; l_hi *= corr_hi;
#pragma unroll
        for (int n = 0; n < 8; n++) {
            Oa[n][0] *= corr_lo; Oa[n][1] *= corr_lo;
            Oa[n][2] *= corr_hi; Oa[n][3] *= corr_hi;
        }
        uint32_t ph[4][4];
#pragma unroll
        for (int n = 0; n < 8; n++) {
            float p0 = ex2f(c[n][0] - mn_lo);
            float p1 = ex2f(c[n][1] - mn_lo);
            float p2 = ex2f(c[n][2] - mn_hi);
            float p3 = ex2f(c[n][3] - mn_hi);
            __half2 h01 = __floats2half2_rn(p0, p1);
            __half2 h23 = __floats2half2_rn(p2, p3);
            float2 f01 = __half22float2(h01);
            float2 f23 = __half22float2(h23);
            l_lo += f01.x + f01.y;
            l_hi += f23.x + f23.y;
            int kc = n >> 1, o = (n & 1) * 2;
            ph[kc][o]     = *reinterpret_cast<uint32_t*>(&h01);
            ph[kc][o + 1] = *reinterpret_cast<uint32_t*>(&h23);
        }

        // ---- O += P V (single-V) ---------------------------------------------
#pragma unroll
        for (int np = 0; np < 4; np++) {
            uint32_t baseH = cb + VH_O + brow + np * (16 * SKB);
#pragma unroll
            for (int k = 0; k < 4; k++) {
                uint32_t vhh[4];
                ldm_x4(vhh, baseH + k * 32);
                mma16816(Oa[2 * np],     ph[k], vhh);
                mma16816(Oa[2 * np + 1], ph[k], vhh + 2);
            }
        }
        __syncthreads();
    }

    // ---- epilogue: normalize + fp16 pack write -------------------------------
    l_lo += __shfl_xor_sync(0xffffffffu, l_lo, 1);
    l_lo += __shfl_xor_sync(0xffffffffu, l_lo, 2);
    l_hi += __shfl_xor_sync(0xffffffffu, l_hi, 1);
    l_hi += __shfl_xor_sync(0xffffffffu, l_hi, 2);
    float inv_lo = 1.f / l_lo, inv_hi = 1.f / l_hi;

    int r = lane >> 2, cc = (lane & 3) * 2;
    size_t base_lo = ((size_t)(q0 + 16 * wid + r) * Nb + nb) * E + h * HD;
    size_t base_hi = ((size_t)(q0 + 16 * wid + r + 8) * Nb + nb) * E + h * HD;
#pragma unroll
    for (int n = 0; n < 8; n++) {
        int d = n * 8 + cc;
        ((uint32_t*)g_of)[(base_lo + d) >> 1] =
            pack2h(Oa[n][0] * inv_lo, Oa[n][1] * inv_lo);
        ((uint32_t*)g_of)[(base_hi + d) >> 1] =
            pack2h(Oa[n][2] * inv_hi, Oa[n][3] * inv_hi);
    }
}

// ---------------- launcher ---------------------------------------------------
extern "C" void kernel_launch(void* const* d_in, const int* in_sizes, int n_in,
                              void* d_out, int out_size)
{
    const float* query = (const float*)d_in[0];
    const float* key   = (const float*)d_in[1];
    const float* value = (const float*)d_in[2];
    const float* in_w  = (const float*)d_in[3];
    const float* in_b  = (const float*)d_in[4];
    const float* q_dn  = (const float*)d_in[5];
    const float* q_up  = (const float*)d_in[6];
    const float* k_dn  = (const float*)d_in[7];
    const float* k_up  = (const float*)d_in[8];
    const float* v_dn  = (const float*)d_in[9];
    const float* v_up  = (const float*)d_in[10];
    const float* out_w = (const float*)d_in[11];
    const float* out_b = (const float*)d_in[12];
    const float* o_dn  = (const float*)d_in[13];
    const float* o_up  = (const float*)d_in[14];

    __half *p_wh, *p_wl, *p_xf, *p_of;
    cudaGetSymbolAddress((void**)&p_wh, g_wh);
    cudaGetSymbolAddress((void**)&p_wl, g_wl);
    cudaGetSymbolAddress((void**)&p_xf, g_xf);
    cudaGetSymbolAddress((void**)&p_of, g_of);

    cudaFuncSetAttribute(attn_mma3,
                         cudaFuncAttributeMaxDynamicSharedMemorySize, S_TOTAL3);
    cudaFuncSetAttribute(gemm_mma,
                         cudaFuncAttributeMaxDynamicSharedMemorySize, G_SMEM);

    // 1) W_eff -> fp16 hi/lo + input fp16 pack
    weff_split_kernel<<<WEFF_BLOCKS + XSPL_BLOCKS, 256>>>(
        in_w, out_w, q_dn, q_up, k_dn, k_up, v_dn, v_up, o_dn, o_up,
        query, key, value);
    // 2) QKV projections; q/k written directly in attention fp16 layout
    gemm_mma<<<dim3(E / 128, Mrows / 128, 3), 256, G_SMEM>>>(
        p_xf, p_wh, p_wl, in_b, nullptr, /*mode=*/1);
    // 3) v transpose to fp16 [bh][d][L]
    v_prep<<<dim3(Ldim / 64, BH), 256>>>();
    // 4) warp-MMA flash attention (launch #4 -> profiled); writes g_of
    attn_mma3<<<dim3(Ldim / 64, BH), 128, S_TOTAL3>>>();
    // 5) output projection -> d_out (fp32)
    gemm_mma<<<dim3(E / 128, Mrows / 128, 1), 256, G_SMEM>>>(
        p_of, p_wh + 3 * (size_t)EE, p_wl + 3 * (size_t)EE, out_b,
        (float*)d_out, /*mode=*/0);
}

// round 13
// speedup vs baseline: 2.0202x; 1.2410x over previous
#include <cuda_runtime.h>
#include <cuda_fp16.h>
#include <math.h>
#include <stdint.h>

#define Ldim 2048
#define Nb   4
#define E    768
#define H    12
#define HD   64
#define BH   (Nb*H)         /* 48 */
#define Mrows (Ldim*Nb)     /* 8192 */
#define EE   (E*E)          /* 589824 */
#define MK   (Mrows*E)      /* 6291456 */

// ---------------- scratch (static device globals; no runtime allocation) ----
__device__ float g_v[MK];
// fp16 operands: weights hi/lo [z][e][k]; activations single [z][m][k]
__device__ __half g_wh[4*EE], g_wl[4*EE];
__device__ __half g_xf[3*MK];
__device__ __half g_of[MK];
// attention operands (all single fp16): q,k [bh][l][64]; v transposed [bh][d][L]
__device__ __half g_qf[BH*Ldim*HD];
__device__ __half g_kh[BH*Ldim*HD];
__device__ __half g_vth[BH*HD*Ldim];

// ============================ helpers ========================================
__device__ __forceinline__ uint32_t smem_u32(const void* p) {
    uint32_t a;
    asm("{ .reg .u64 t; cvta.to.shared.u64 t, %1; cvt.u32.u64 %0, t; }"
        : "=r"(a) : "l"(p));
    return a;
}
__device__ __forceinline__ float ex2f(float x) {
    float y; asm("ex2.approx.f32 %0, %1;" : "=f"(y) : "f"(x)); return y;
}
#define STS128(addr, r0, r1, r2, r3) \
    asm volatile("st.shared.v4.b32 [%0], {%1, %2, %3, %4};" \
                 :: "r"(addr), "r"(r0), "r"(r1), "r"(r2), "r"(r3) : "memory")

__device__ __forceinline__ void cpa16(uint32_t dst, const void* src) {
    asm volatile("cp.async.cg.shared.global [%0], [%1], 16;"
                 :: "r"(dst), "l"(src) : "memory");
}
#define CP_COMMIT() asm volatile("cp.async.commit_group;" ::: "memory")
#define CP_WAIT1()  asm volatile("cp.async.wait_group 1;" ::: "memory")
#define CP_WAIT0()  asm volatile("cp.async.wait_group 0;" ::: "memory")

__device__ __forceinline__ void ldm_x4(uint32_t* r, uint32_t addr) {
    asm volatile("ldmatrix.sync.aligned.m8n8.x4.shared.b16 {%0,%1,%2,%3}, [%4];"
                 : "=r"(r[0]), "=r"(r[1]), "=r"(r[2]), "=r"(r[3]) : "r"(addr));
}
// fp16 MMA, fp32 accumulate
__device__ __forceinline__ void mma16816(float* c, const uint32_t* a,
                                         const uint32_t* b) {
    asm volatile(
        "mma.sync.aligned.m16n8k16.row.col.f32.f16.f16.f32 "
        "{%0,%1,%2,%3}, {%4,%5,%6,%7}, {%8,%9}, {%0,%1,%2,%3};"
        : "+f"(c[0]), "+f"(c[1]), "+f"(c[2]), "+f"(c[3])
        : "r"(a[0]), "r"(a[1]), "r"(a[2]), "r"(a[3]), "r"(b[0]), "r"(b[1]));
}
// fp16 hi/lo split of a float pair (elem0 in low half)
__device__ __forceinline__ void split2h(float a, float b, uint32_t& hi, uint32_t& lo) {
    __half2 h = __floats2half2_rn(a, b);
    float2 hf = __half22float2(h);
    __half2 l = __floats2half2_rn(a - hf.x, b - hf.y);
    hi = *reinterpret_cast<uint32_t*>(&h);
    lo = *reinterpret_cast<uint32_t*>(&l);
}
__device__ __forceinline__ uint32_t pack2h(float a, float b) {
    __half2 h = __floats2half2_rn(a, b);
    return *reinterpret_cast<uint32_t*>(&h);
}

// ---------------- combined: W_eff fp16 split + x fp16 pack -------------------
#define WEFF_BLOCKS 4608            /* 4 * EE/2 / 256 */
#define XSPL_BLOCKS 18432           /* 3 * MK/4 / 256 */

__global__ void __launch_bounds__(256) weff_split_kernel(
    const float* __restrict__ inW,  const float* __restrict__ outW,
    const float* __restrict__ qd, const float* __restrict__ qu,
    const float* __restrict__ kd, const float* __restrict__ ku,
    const float* __restrict__ vd, const float* __restrict__ vu,
    const float* __restrict__ od, const float* __restrict__ ou,
    const float* __restrict__ query, const float* __restrict__ key,
    const float* __restrict__ value)
{
    int bx = blockIdx.x;
    if (bx < WEFF_BLOCKS) {
        int z = bx / (WEFF_BLOCKS / 4);
        int pidx = (bx % (WEFF_BLOCKS / 4)) * 256 + threadIdx.x;  // pair idx < EE/2
        int e = (pidx * 2) / E;
        int k = (pidx * 2) % E;
        const float* W  = (z < 3) ? (inW + z * EE) : outW;
        const float* dn = (z == 0) ? qd : (z == 1) ? kd : (z == 2) ? vd : od;
        const float* up = (z == 0) ? qu : (z == 1) ? ku : (z == 2) ? vu : ou;
        float s0 = 0.f, s1 = 0.f;
#pragma unroll
        for (int r = 0; r < 16; r++) {
            float u = up[e * 16 + r];
            s0 += u * dn[r * E + k];
            s1 += u * dn[r * E + k + 1];
        }
        float v0 = W[e * E + k] + s0;
        float v1 = W[e * E + k + 1] + s1;
        uint32_t hi, lo;
        split2h(v0, v1, hi, lo);
        ((uint32_t*)g_wh)[(size_t)z * (EE / 2) + pidx] = hi;
        ((uint32_t*)g_wl)[(size_t)z * (EE / 2) + pidx] = lo;
    } else {
        int i = bx - WEFF_BLOCKS;
        int z = i / (XSPL_BLOCKS / 3);
        size_t idx = (size_t)(i % (XSPL_BLOCKS / 3)) * 256 + threadIdx.x;  // float4 idx
        const float4* src = (const float4*)((z == 0) ? query : (z == 1) ? key : value);
        float4 v = src[idx];
        ((uint2*)g_xf)[(size_t)z * (MK / 4) + idx] =
            make_uint2(pack2h(v.x, v.y), pack2h(v.z, v.w));
    }
}

// ================= fp16 MMA GEMM =============================================
// passes=1: W single (g_wh only).  passes=2: W hi/lo.
// mode 0: write fp32 yout.  mode 1 (QKV): z<2 -> g_qf/g_kh fp16 [bh][l][64],
// z=2 -> fp32 g_v.
#define SKG 80                 /* smem row stride bytes (32 fp16 + pad) */
#define GA_F 0
#define GB_H 10240
#define GB_L 20480
#define GSTG 30720
#define G_SMEM (2*GSTG)        /* 61440 */
#define GKT (E/32)             /* 24 k-stages */

__device__ __forceinline__ void g_prefetch(
    uint32_t buf,
    const __half* axf, const __half* bwh, const __half* bwl,
    int m0, int e0, int k0, int tid, int passes)
{
    int row = tid >> 1, part = tid & 1;
    uint32_t ro = (uint32_t)row * SKG + (uint32_t)part * 32;
    const __half* af = axf + (size_t)(m0 + row) * E + k0 + part * 16;
    const __half* bh = bwh + (size_t)(e0 + row) * E + k0 + part * 16;
    cpa16(buf + GA_F + ro,      af); cpa16(buf + GA_F + ro + 16, af + 8);
    cpa16(buf + GB_H + ro,      bh); cpa16(buf + GB_H + ro + 16, bh + 8);
    if (passes == 2) {
        const __half* bl = bwl + (size_t)(e0 + row) * E + k0 + part * 16;
        cpa16(buf + GB_L + ro,      bl); cpa16(buf + GB_L + ro + 16, bl + 8);
    }
}

__global__ void __launch_bounds__(256, 2) gemm_mma(
    const __half* __restrict__ xf,
    const __half* __restrict__ wh, const __half* __restrict__ wl,
    const float* __restrict__ bias_base,
    float* __restrict__ yout,
    int mode, int passes)
{
    extern __shared__ __align__(128) char smem[];
    uint32_t sb = smem_u32(smem);
    int z = blockIdx.z;
    const __half* axf = xf + (size_t)z * MK;
    const __half* bwh = wh + (size_t)z * EE;
    const __half* bwl = wl + (size_t)z * EE;
    const float* bias = bias_base + z * E;
    int m0 = blockIdx.y * 128, e0 = blockIdx.x * 128;
    int tid = threadIdx.x, wid = tid >> 5, lane = tid & 31;
    int wm = wid & 1, wn = wid >> 1;

    uint32_t arow = (uint32_t)(wm * 64 + (lane & 15)) * SKG + (uint32_t)(lane >> 4) * 16;
    uint32_t brow = (uint32_t)(wn * 32 + (lane >> 4) * 8 + (lane & 7)) * SKG
                  + (uint32_t)((lane >> 3) & 1) * 16;

    float acc[4][4][4];
#pragma unroll
    for (int a = 0; a < 4; a++)
#pragma unroll
        for (int b = 0; b < 4; b++)
#pragma unroll
            for (int c = 0; c < 4; c++) acc[a][b][c] = 0.f;

    g_prefetch(sb, axf, bwh, bwl, m0, e0, 0, tid, passes);
    CP_COMMIT();

    for (int kt = 0; kt < GKT; kt++) {
        uint32_t cb = sb + (uint32_t)(kt & 1) * GSTG;
        if (kt + 1 < GKT) {
            g_prefetch(sb + (uint32_t)((kt + 1) & 1) * GSTG,
                       axf, bwh, bwl, m0, e0, (kt + 1) * 32, tid, passes);
            CP_COMMIT();
            CP_WAIT1();
        } else {
            CP_WAIT0();
        }
        __syncthreads();
#pragma unroll
        for (int ks = 0; ks < 2; ks++) {
            uint32_t koff = (uint32_t)ks * 32;
            uint32_t bhf[2][4], blf[2][4];
            ldm_x4(bhf[0], cb + GB_H + brow + koff);
            ldm_x4(bhf[1], cb + GB_H + brow + 16 * SKG + koff);
            if (passes == 2) {
                ldm_x4(blf[0], cb + GB_L + brow + koff);
                ldm_x4(blf[1], cb + GB_L + brow + 16 * SKG + koff);
            }
#pragma unroll
            for (int mi = 0; mi < 4; mi++) {
                uint32_t af[4];
                ldm_x4(af, cb + GA_F + arow + mi * 16 * SKG + koff);
#pragma unroll
                for (int ni = 0; ni < 4; ni++) {
                    const uint32_t* bfh = bhf[ni >> 1] + (ni & 1) * 2;
                    mma16816(acc[mi][ni], af, bfh);
                    if (passes == 2) {
                        const uint32_t* bfl = blf[ni >> 1] + (ni & 1) * 2;
                        mma16816(acc[mi][ni], af, bfl);
                    }
                }
            }
        }
        __syncthreads();
    }

    int r = lane >> 2, cp = (lane & 3) * 2;
    if (mode == 1 && z < 2) {
        // fused attention-format epilogue: [bh][l][64] fp16 pack
        float qs = (z == 0) ? 0.125f * 1.4426950408889634f : 1.0f;
        __half* dst = (z == 0) ? g_qf : g_kh;
#pragma unroll
        for (int mi = 0; mi < 4; mi++) {
#pragma unroll
            for (int ni = 0; ni < 4; ni++) {
                int col = e0 + wn * 32 + ni * 8 + cp;
                int hh = col >> 6, d = col & 63;
                float b0 = bias[col], b1 = bias[col + 1];
#pragma unroll
                for (int rr = 0; rr < 2; rr++) {
                    int row = m0 + wm * 64 + mi * 16 + r + rr * 8;
                    int l = row >> 2, nb = row & 3;
                    size_t w = ((((size_t)(nb * H + hh) * Ldim + l) * HD) + d) >> 1;
                    float a = (acc[mi][ni][2 * rr]     + b0) * qs;
                    float b = (acc[mi][ni][2 * rr + 1] + b1) * qs;
                    ((uint32_t*)dst)[w] = pack2h(a, b);
                }
            }
        }
    } else {
        float* y = (mode == 1) ? g_v : yout;
#pragma unroll
        for (int mi = 0; mi < 4; mi++) {
            int row0 = m0 + wm * 64 + mi * 16 + r;
#pragma unroll
            for (int ni = 0; ni < 4; ni++) {
                int col = e0 + wn * 32 + ni * 8 + cp;
                float b0 = bias[col], b1 = bias[col + 1];
                float2 v0 = make_float2(acc[mi][ni][0] + b0, acc[mi][ni][1] + b1);
                float2 v1 = make_float2(acc[mi][ni][2] + b0, acc[mi][ni][3] + b1);
                *(float2*)(y + (size_t)row0 * E + col) = v0;
                *(float2*)(y + (size_t)(row0 + 8) * E + col) = v1;
            }
        }
    }
}

// ---------------- prep: v -> transposed fp16 [bh][d][L] ----------------------
__global__ void __launch_bounds__(256) v_prep()
{
    __shared__ float vt[64][65];
    int bh = blockIdx.y;
    int s0 = blockIdx.x * 64;
    int nb = bh / H, h = bh % H;
    int t = threadIdx.x;
    {
        int s = t >> 2, dq = (t & 3) * 16;
        const float* src = g_v + ((size_t)(s0 + s) * Nb + nb) * E + h * HD + dq;
#pragma unroll
        for (int j = 0; j < 4; j++) {
            float4 v = *(const float4*)(src + j * 4);
            vt[s][dq + j * 4 + 0] = v.x;
            vt[s][dq + j * 4 + 1] = v.y;
            vt[s][dq + j * 4 + 2] = v.z;
            vt[s][dq + j * 4 + 3] = v.w;
        }
    }
    __syncthreads();
    {
        int d = t >> 2, sq = (t & 3) * 16;
        uint32_t hw[8];
#pragma unroll
        for (int j = 0; j < 8; j++)
            hw[j] = pack2h(vt[sq + 2 * j][d], vt[sq + 2 * j + 1][d]);
        size_t dst = ((size_t)bh * HD + d) * Ldim + s0 + sq;
        ((uint4*)(g_vth + dst))[0] = make_uint4(hw[0], hw[1], hw[2], hw[3]);
        ((uint4*)(g_vth + dst))[1] = make_uint4(hw[4], hw[5], hw[6], hw[7]);
    }
}

// ================= warp-MMA flash attention (fp16 single K and V) ============
#define SKB 144
#define STAGE_B 18432          /* KH 9216 + VH 9216 */
#define KH_O 0
#define VH_O 9216
#define S_TOTAL3 (2*STAGE_B)   /* 36864 */
#define NT (Ldim / 64)

__device__ __forceinline__ void kv_prefetch(uint32_t buf, int bh, int s0, int tid)
{
    int m = tid >> 1;
    int hf = tid & 1;
    uint32_t ro = (uint32_t)m * SKB + (uint32_t)hf * 64;
    const __half* kh = g_kh + ((size_t)bh * Ldim + s0 + m) * HD + hf * 32;
    const __half* vh = g_vth + ((size_t)bh * HD + m) * Ldim + s0 + hf * 32;
#pragma unroll
    for (int c = 0; c < 4; c++) {
        cpa16(buf + KH_O + ro + c * 16, kh + c * 8);
        cpa16(buf + VH_O + ro + c * 16, vh + c * 8);
    }
}

__global__ void __launch_bounds__(128, 4) attn_mma3()
{
    extern __shared__ __align__(128) char smem[];
    uint32_t sb = smem_u32(smem);
    int tid = threadIdx.x;
    int wid = tid >> 5, lane = tid & 31;
    int bh = blockIdx.y;
    int nb = bh / H, h = bh % H;
    int q0 = blockIdx.x * 64;

    kv_prefetch(sb, bh, 0, tid);
    CP_COMMIT();

    // stage Q through stage-1 buffer (transient)
    {
        uint32_t q_s = sb + STAGE_B;
        int m = tid >> 1;
        int u0 = (tid & 1) * 4;
        uint32_t o = (uint32_t)m * SKB + (uint32_t)u0 * 16;
        const uint4* s = (const uint4*)(g_qf + ((size_t)bh * Ldim + q0 + m) * HD) + u0;
        uint4 a = s[0], b = s[1], c = s[2], d = s[3];
        STS128(q_s + o,      a.x, a.y, a.z, a.w);
        STS128(q_s + o + 16, b.x, b.y, b.z, b.w);
        STS128(q_s + o + 32, c.x, c.y, c.z, c.w);
        STS128(q_s + o + 48, d.x, d.y, d.z, d.w);
    }
    __syncthreads();

    uint32_t qrow = (uint32_t)(16 * wid + (lane & 15)) * SKB + (uint32_t)(lane >> 4) * 16;
    uint32_t brow = (uint32_t)(((lane >> 4) * 8 + (lane & 7))) * SKB
                  + (uint32_t)((lane >> 3) & 1) * 16;

    uint32_t qf[4][4];
#pragma unroll
    for (int k = 0; k < 4; k++)
        ldm_x4(qf[k], sb + STAGE_B + qrow + k * 32);
    __syncthreads();

    float Oa[8][4];
#pragma unroll
    for (int n = 0; n < 8; n++)
#pragma unroll
        for (int j = 0; j < 4; j++) Oa[n][j] = 0.f;
    float m_lo = -INFINITY, m_hi = -INFINITY, l_lo = 0.f, l_hi = 0.f;

    for (int t = 0; t < NT; t++) {
        uint32_t cb = sb + (uint32_t)(t & 1) * STAGE_B;
        if (t + 1 < NT) {
            kv_prefetch(sb + (uint32_t)((t + 1) & 1) * STAGE_B,
                        bh, (t + 1) * 64, tid);
            CP_COMMIT();
            CP_WAIT1();
        } else {
            CP_WAIT0();
        }
        __syncthreads();

        // ---- S = Q K^T (single-K) --------------------------------------------
        float c[8][4];
#pragma unroll
        for (int n = 0; n < 8; n++)
#pragma unroll
            for (int j = 0; j < 4; j++) c[n][j] = 0.f;
#pragma unroll
        for (int np = 0; np < 4; np++) {
            uint32_t baseH = cb + KH_O + brow + np * (16 * SKB);
#pragma unroll
            for (int k = 0; k < 4; k++) {
                uint32_t bhh[4];
                ldm_x4(bhh, baseH + k * 32);
                mma16816(c[2 * np],     qf[k], bhh);
                mma16816(c[2 * np + 1], qf[k], bhh + 2);
            }
        }

        // ---- online softmax (quad-local rows) -------------------------------
        float mn_lo = m_lo, mn_hi = m_hi;
#pragma unroll
        for (int n = 0; n < 8; n++) {
            mn_lo = fmaxf(mn_lo, fmaxf(c[n][0], c[n][1]));
            mn_hi = fmaxf(mn_hi, fmaxf(c[n][2], c[n][3]));
        }
        mn_lo = fmaxf(mn_lo, __shfl_xor_sync(0xffffffffu, mn_lo, 1));
        mn_lo = fmaxf(mn_lo, __shfl_xor_sync(0xffffffffu, mn_lo, 2));
        mn_hi = fmaxf(mn_hi, __shfl_xor_sync(0xffffffffu, mn_hi, 1));
        mn_hi = fmaxf(mn_hi, __shfl_xor_sync(0xffffffffu, mn_hi, 2));
        float corr_lo = ex2f(m_lo - mn_lo);
        float corr_hi = ex2f(m_hi - mn_hi);
        m_lo = mn_lo; m_hi = mn_hi;
        l_lo *= corr_lo; l_hi *= corr_hi;
#pragma unroll
        for (int n = 0; n < 8; n++) {
            Oa[n][0] *= corr_lo; Oa[n][1] *= corr_lo;
            Oa[n][2] *= corr_hi; Oa[n][3] *= corr_hi;
        }
        uint32_t ph[4][4];
#pragma unroll
        for (int n = 0; n < 8; n++) {
            float p0 = ex2f(c[n][0] - mn_lo);
            float p1 = ex2f(c[n][1] - mn_lo);
            float p2 = ex2f(c[n][2] - mn_hi);
            float p3 = ex2f(c[n][3] - mn_hi);
            __half2 h01 = __floats2half2_rn(p0, p1);
            __half2 h23 = __floats2half2_rn(p2, p3);
            float2 f01 = __half22float2(h01);
            float2 f23 = __half22float2(h23);
            l_lo += f01.x + f01.y;
            l_hi += f23.x + f23.y;
            int kc = n >> 1, o = (n & 1) * 2;
            ph[kc][o]     = *reinterpret_cast<uint32_t*>(&h01);
            ph[kc][o + 1] = *reinterpret_cast<uint32_t*>(&h23);
        }

        // ---- O += P V (single-V) ---------------------------------------------
#pragma unroll
        for (int np = 0; np < 4; np++) {
            uint32_t baseH = cb + VH_O + brow + np * (16 * SKB);
#pragma unroll
            for (int k = 0; k < 4; k++) {
                uint32_t vhh[4];
                ldm_x4(vhh, baseH + k * 32);
                mma16816(Oa[2 * np],     ph[k], vhh);
                mma16816(Oa[2 * np + 1], ph[k], vhh + 2);
            }
        }
        __syncthreads();
    }

    // ---- epilogue: normalize + fp16 pack write -------------------------------
    l_lo += __shfl_xor_sync(0xffffffffu, l_lo, 1);
    l_lo += __shfl_xor_sync(0xffffffffu, l_lo, 2);
    l_hi += __shfl_xor_sync(0xffffffffu, l_hi, 1);
    l_hi += __shfl_xor_sync(0xffffffffu, l_hi, 2);
    float inv_lo = 1.f / l_lo, inv_hi = 1.f / l_hi;

    int r = lane >> 2, cc = (lane & 3) * 2;
    size_t base_lo = ((size_t)(q0 + 16 * wid + r) * Nb + nb) * E + h * HD;
    size_t base_hi = ((size_t)(q0 + 16 * wid + r + 8) * Nb + nb) * E + h * HD;
#pragma unroll
    for (int n = 0; n < 8; n++) {
        int d = n * 8 + cc;
        ((uint32_t*)g_of)[(base_lo + d) >> 1] =
            pack2h(Oa[n][0] * inv_lo, Oa[n][1] * inv_lo);
        ((uint32_t*)g_of)[(base_hi + d) >> 1] =
            pack2h(Oa[n][2] * inv_hi, Oa[n][3] * inv_hi);
    }
}

// ---------------- launcher ---------------------------------------------------
extern "C" void kernel_launch(void* const* d_in, const int* in_sizes, int n_in,
                              void* d_out, int out_size)
{
    const float* query = (const float*)d_in[0];
    const float* key   = (const float*)d_in[1];
    const float* value = (const float*)d_in[2];
    const float* in_w  = (const float*)d_in[3];
    const float* in_b  = (const float*)d_in[4];
    const float* q_dn  = (const float*)d_in[5];
    const float* q_up  = (const float*)d_in[6];
    const float* k_dn  = (const float*)d_in[7];
    const float* k_up  = (const float*)d_in[8];
    const float* v_dn  = (const float*)d_in[9];
    const float* v_up  = (const float*)d_in[10];
    const float* out_w = (const float*)d_in[11];
    const float* out_b = (const float*)d_in[12];
    const float* o_dn  = (const float*)d_in[13];
    const float* o_up  = (const float*)d_in[14];

    __half *p_wh, *p_wl, *p_xf, *p_of;
    cudaGetSymbolAddress((void**)&p_wh, g_wh);
    cudaGetSymbolAddress((void**)&p_wl, g_wl);
    cudaGetSymbolAddress((void**)&p_xf, g_xf);
    cudaGetSymbolAddress((void**)&p_of, g_of);

    cudaFuncSetAttribute(attn_mma3,
                         cudaFuncAttributeMaxDynamicSharedMemorySize, S_TOTAL3);
    cudaFuncSetAttribute(gemm_mma,
                         cudaFuncAttributeMaxDynamicSharedMemorySize, G_SMEM);

    // 1) W_eff -> fp16 hi/lo + input fp16 pack
    weff_split_kernel<<<WEFF_BLOCKS + XSPL_BLOCKS, 256>>>(
        in_w, out_w, q_dn, q_up, k_dn, k_up, v_dn, v_up, o_dn, o_up,
        query, key, value);
    // 2) QKV projections, single-pass W; q/k written in attention fp16 layout
    gemm_mma<<<dim3(E / 128, Mrows / 128, 3), 256, G_SMEM>>>(
        p_xf, p_wh, p_wl, in_b, nullptr, /*mode=*/1, /*passes=*/1);
    // 3) v transpose to fp16 [bh][d][L]
    v_prep<<<dim3(Ldim / 64, BH), 256>>>();
    // 4) warp-MMA flash attention (launch #4 -> profiled); writes g_of
    attn_mma3<<<dim3(Ldim / 64, BH), 128, S_TOTAL3>>>();
    // 5) output projection (W hi/lo 2-pass) -> d_out (fp32)
    gemm_mma<<<dim3(E / 128, Mrows / 128, 1), 256, G_SMEM>>>(
        p_of, p_wh + 3 * (size_t)EE, p_wl + 3 * (size_t)EE, out_b,
        (float*)d_out, /*mode=*/0, /*passes=*/2);
}

// round 14
// speedup vs baseline: 2.3475x; 1.1620x over previous
#include <cuda_runtime.h>
#include <cuda_fp16.h>
#include <math.h>
#include <stdint.h>

#define Ldim 2048
#define Nb   4
#define E    768
#define H    12
#define HD   64
#define BH   (Nb*H)         /* 48 */
#define Mrows (Ldim*Nb)     /* 8192 */
#define EE   (E*E)          /* 589824 */
#define MK   (Mrows*E)      /* 6291456 */

// ---------------- scratch (static device globals; no runtime allocation) ----
__device__ float g_v[MK];
// fp16 operands: weights single [z][e][k]; activations single [z][m][k]
__device__ __half g_wh[4*EE];
__device__ __half g_xf[3*MK];
__device__ __half g_of[MK];
// attention operands (all single fp16): q,k [bh][l][64]; v transposed [bh][d][L]
__device__ __half g_qf[BH*Ldim*HD];
__device__ __half g_kh[BH*Ldim*HD];
__device__ __half g_vth[BH*HD*Ldim];

// ============================ helpers ========================================
__device__ __forceinline__ uint32_t smem_u32(const void* p) {
    uint32_t a;
    asm("{ .reg .u64 t; cvta.to.shared.u64 t, %1; cvt.u32.u64 %0, t; }"
        : "=r"(a) : "l"(p));
    return a;
}
__device__ __forceinline__ float ex2f(float x) {
    float y; asm("ex2.approx.f32 %0, %1;" : "=f"(y) : "f"(x)); return y;
}
#define STS128(addr, r0, r1, r2, r3) \
    asm volatile("st.shared.v4.b32 [%0], {%1, %2, %3, %4};" \
                 :: "r"(addr), "r"(r0), "r"(r1), "r"(r2), "r"(r3) : "memory")

__device__ __forceinline__ void cpa16(uint32_t dst, const void* src) {
    asm volatile("cp.async.cg.shared.global [%0], [%1], 16;"
                 :: "r"(dst), "l"(src) : "memory");
}
#define CP_COMMIT() asm volatile("cp.async.commit_group;" ::: "memory")
#define CP_WAIT1()  asm volatile("cp.async.wait_group 1;" ::: "memory")
#define CP_WAIT0()  asm volatile("cp.async.wait_group 0;" ::: "memory")

__device__ __forceinline__ void ldm_x4(uint32_t* r, uint32_t addr) {
    asm volatile("ldmatrix.sync.aligned.m8n8.x4.shared.b16 {%0,%1,%2,%3}, [%4];"
                 : "=r"(r[0]), "=r"(r[1]), "=r"(r[2]), "=r"(r[3]) : "r"(addr));
}
__device__ __forceinline__ void ldm_x2(uint32_t* r, uint32_t addr) {
    asm volatile("ldmatrix.sync.aligned.m8n8.x2.shared.b16 {%0,%1}, [%2];"
                 : "=r"(r[0]), "=r"(r[1]) : "r"(addr));
}
// fp16 MMA, fp32 accumulate
__device__ __forceinline__ void mma16816(float* c, const uint32_t* a,
                                         const uint32_t* b) {
    asm volatile(
        "mma.sync.aligned.m16n8k16.row.col.f32.f16.f16.f32 "
        "{%0,%1,%2,%3}, {%4,%5,%6,%7}, {%8,%9}, {%0,%1,%2,%3};"
        : "+f"(c[0]), "+f"(c[1]), "+f"(c[2]), "+f"(c[3])
        : "r"(a[0]), "r"(a[1]), "r"(a[2]), "r"(a[3]), "r"(b[0]), "r"(b[1]));
}
__device__ __forceinline__ uint32_t pack2h(float a, float b) {
    __half2 h = __floats2half2_rn(a, b);
    return *reinterpret_cast<uint32_t*>(&h);
}

// ---------------- combined: W_eff fp16 pack + x fp16 pack --------------------
#define WEFF_BLOCKS 4608            /* 4 * EE/2 / 256 */
#define XSPL_BLOCKS 18432           /* 3 * MK/4 / 256 */

__global__ void __launch_bounds__(256) weff_split_kernel(
    const float* __restrict__ inW,  const float* __restrict__ outW,
    const float* __restrict__ qd, const float* __restrict__ qu,
    const float* __restrict__ kd, const float* __restrict__ ku,
    const float* __restrict__ vd, const float* __restrict__ vu,
    const float* __restrict__ od, const float* __restrict__ ou,
    const float* __restrict__ query, const float* __restrict__ key,
    const float* __restrict__ value)
{
    int bx = blockIdx.x;
    if (bx < WEFF_BLOCKS) {
        int z = bx / (WEFF_BLOCKS / 4);
        int pidx = (bx % (WEFF_BLOCKS / 4)) * 256 + threadIdx.x;  // pair idx < EE/2
        int e = (pidx * 2) / E;
        int k = (pidx * 2) % E;
        const float* W  = (z < 3) ? (inW + z * EE) : outW;
        const float* dn = (z == 0) ? qd : (z == 1) ? kd : (z == 2) ? vd : od;
        const float* up = (z == 0) ? qu : (z == 1) ? ku : (z == 2) ? vu : ou;
        float s0 = 0.f, s1 = 0.f;
#pragma unroll
        for (int r = 0; r < 16; r++) {
            float u = up[e * 16 + r];
            s0 += u * dn[r * E + k];
            s1 += u * dn[r * E + k + 1];
        }
        float v0 = W[e * E + k] + s0;
        float v1 = W[e * E + k + 1] + s1;
        ((uint32_t*)g_wh)[(size_t)z * (EE / 2) + pidx] = pack2h(v0, v1);
    } else {
        int i = bx - WEFF_BLOCKS;
        int z = i / (XSPL_BLOCKS / 3);
        size_t idx = (size_t)(i % (XSPL_BLOCKS / 3)) * 256 + threadIdx.x;  // float4 idx
        const float4* src = (const float4*)((z == 0) ? query : (z == 1) ? key : value);
        float4 v = src[idx];
        ((uint2*)g_xf)[(size_t)z * (MK / 4) + idx] =
            make_uint2(pack2h(v.x, v.y), pack2h(v.z, v.w));
    }
}

// ================= fp16 single-pass MMA GEMM =================================
// mode 0: write fp32 yout.  mode 1 (QKV): z<2 -> g_qf/g_kh fp16 [bh][l][64],
// z=2 -> fp32 g_v.
#define SKG 80                 /* smem row stride bytes (32 fp16 + pad) */
#define GA_F 0
#define GB_H 10240
#define GSTG 20480
#define G_SMEM (2*GSTG)        /* 40960 */
#define GKT (E/32)             /* 24 k-stages */

__device__ __forceinline__ void g_prefetch(
    uint32_t buf, const __half* axf, const __half* bwh,
    int m0, int e0, int k0, int tid)
{
    int row = tid >> 1, part = tid & 1;
    uint32_t ro = (uint32_t)row * SKG + (uint32_t)part * 32;
    const __half* af = axf + (size_t)(m0 + row) * E + k0 + part * 16;
    const __half* bh = bwh + (size_t)(e0 + row) * E + k0 + part * 16;
    cpa16(buf + GA_F + ro,      af); cpa16(buf + GA_F + ro + 16, af + 8);
    cpa16(buf + GB_H + ro,      bh); cpa16(buf + GB_H + ro + 16, bh + 8);
}

__global__ void __launch_bounds__(256, 2) gemm_mma(
    const __half* __restrict__ xf, const __half* __restrict__ wh,
    const float* __restrict__ bias_base,
    float* __restrict__ yout, int mode)
{
    extern __shared__ __align__(128) char smem[];
    uint32_t sb = smem_u32(smem);
    int z = blockIdx.z;
    const __half* axf = xf + (size_t)z * MK;
    const __half* bwh = wh + (size_t)z * EE;
    const float* bias = bias_base + z * E;
    int m0 = blockIdx.y * 128, e0 = blockIdx.x * 128;
    int tid = threadIdx.x, wid = tid >> 5, lane = tid & 31;
    int wm = wid & 1, wn = wid >> 1;

    uint32_t arow = (uint32_t)(wm * 64 + (lane & 15)) * SKG + (uint32_t)(lane >> 4) * 16;
    uint32_t brow = (uint32_t)(wn * 32 + (lane >> 4) * 8 + (lane & 7)) * SKG
                  + (uint32_t)((lane >> 3) & 1) * 16;

    float acc[4][4][4];
#pragma unroll
    for (int a = 0; a < 4; a++)
#pragma unroll
        for (int b = 0; b < 4; b++)
#pragma unroll
            for (int c = 0; c < 4; c++) acc[a][b][c] = 0.f;

    g_prefetch(sb, axf, bwh, m0, e0, 0, tid);
    CP_COMMIT();

    for (int kt = 0; kt < GKT; kt++) {
        uint32_t cb = sb + (uint32_t)(kt & 1) * GSTG;
        if (kt + 1 < GKT) {
            g_prefetch(sb + (uint32_t)((kt + 1) & 1) * GSTG,
                       axf, bwh, m0, e0, (kt + 1) * 32, tid);
            CP_COMMIT();
            CP_WAIT1();
        } else {
            CP_WAIT0();
        }
        __syncthreads();
#pragma unroll
        for (int ks = 0; ks < 2; ks++) {
            uint32_t koff = (uint32_t)ks * 32;
            uint32_t bhf[2][4];
            ldm_x4(bhf[0], cb + GB_H + brow + koff);
            ldm_x4(bhf[1], cb + GB_H + brow + 16 * SKG + koff);
#pragma unroll
            for (int mi = 0; mi < 4; mi++) {
                uint32_t af[4];
                ldm_x4(af, cb + GA_F + arow + mi * 16 * SKG + koff);
#pragma unroll
                for (int ni = 0; ni < 4; ni++)
                    mma16816(acc[mi][ni], af, bhf[ni >> 1] + (ni & 1) * 2);
            }
        }
        __syncthreads();
    }

    int r = lane >> 2, cp = (lane & 3) * 2;
    if (mode == 1 && z < 2) {
        float qs = (z == 0) ? 0.125f * 1.4426950408889634f : 1.0f;
        __half* dst = (z == 0) ? g_qf : g_kh;
#pragma unroll
        for (int mi = 0; mi < 4; mi++) {
#pragma unroll
            for (int ni = 0; ni < 4; ni++) {
                int col = e0 + wn * 32 + ni * 8 + cp;
                int hh = col >> 6, d = col & 63;
                float b0 = bias[col], b1 = bias[col + 1];
#pragma unroll
                for (int rr = 0; rr < 2; rr++) {
                    int row = m0 + wm * 64 + mi * 16 + r + rr * 8;
                    int l = row >> 2, nb = row & 3;
                    size_t w = ((((size_t)(nb * H + hh) * Ldim + l) * HD) + d) >> 1;
                    float a = (acc[mi][ni][2 * rr]     + b0) * qs;
                    float b = (acc[mi][ni][2 * rr + 1] + b1) * qs;
                    ((uint32_t*)dst)[w] = pack2h(a, b);
                }
            }
        }
    } else {
        float* y = (mode == 1) ? g_v : yout;
#pragma unroll
        for (int mi = 0; mi < 4; mi++) {
            int row0 = m0 + wm * 64 + mi * 16 + r;
#pragma unroll
            for (int ni = 0; ni < 4; ni++) {
                int col = e0 + wn * 32 + ni * 8 + cp;
                float b0 = bias[col], b1 = bias[col + 1];
                float2 v0 = make_float2(acc[mi][ni][0] + b0, acc[mi][ni][1] + b1);
                float2 v1 = make_float2(acc[mi][ni][2] + b0, acc[mi][ni][3] + b1);
                *(float2*)(y + (size_t)row0 * E + col) = v0;
                *(float2*)(y + (size_t)(row0 + 8) * E + col) = v1;
            }
        }
    }
}

// ---------------- prep: v -> transposed fp16 [bh][d][L] ----------------------
__global__ void __launch_bounds__(256) v_prep()
{
    __shared__ float vt[64][65];
    int bh = blockIdx.y;
    int s0 = blockIdx.x * 64;
    int nb = bh / H, h = bh % H;
    int t = threadIdx.x;
    {
        int s = t >> 2, dq = (t & 3) * 16;
        const float* src = g_v + ((size_t)(s0 + s) * Nb + nb) * E + h * HD + dq;
#pragma unroll
        for (int j = 0; j < 4; j++) {
            float4 v = *(const float4*)(src + j * 4);
            vt[s][dq + j * 4 + 0] = v.x;
            vt[s][dq + j * 4 + 1] = v.y;
            vt[s][dq + j * 4 + 2] = v.z;
            vt[s][dq + j * 4 + 3] = v.w;
        }
    }
    __syncthreads();
    {
        int d = t >> 2, sq = (t & 3) * 16;
        uint32_t hw[8];
#pragma unroll
        for (int j = 0; j < 8; j++)
            hw[j] = pack2h(vt[sq + 2 * j][d], vt[sq + 2 * j + 1][d]);
        size_t dst = ((size_t)bh * HD + d) * Ldim + s0 + sq;
        ((uint4*)(g_vth + dst))[0] = make_uint4(hw[0], hw[1], hw[2], hw[3]);
        ((uint4*)(g_vth + dst))[1] = make_uint4(hw[4], hw[5], hw[6], hw[7]);
    }
}

// ================= warp-MMA flash attention ==================================
// K,V single fp16; V tile padded to 72 rows, rows 64-71 = [ones-row; zeros]
// so column 64 of the PV accumulator carries l (exact w.r.t. rounded P).
#define SKB 144
#define STAGE_B 19584          /* KH 9216 + VH 72*144=10368 */
#define KH_O 0
#define VH_O 9216
#define S_TOTAL3 (2*STAGE_B)   /* 39168 */
#define NT (Ldim / 64)

__device__ __forceinline__ void kv_prefetch(uint32_t buf, int bh, int s0, int tid)
{
    int m = tid >> 1;
    int hf = tid & 1;
    uint32_t ro = (uint32_t)m * SKB + (uint32_t)hf * 64;
    const __half* kh = g_kh + ((size_t)bh * Ldim + s0 + m) * HD + hf * 32;
    const __half* vh = g_vth + ((size_t)bh * HD + m) * Ldim + s0 + hf * 32;
#pragma unroll
    for (int c = 0; c < 4; c++) {
        cpa16(buf + KH_O + ro + c * 16, kh + c * 8);
        cpa16(buf + VH_O + ro + c * 16, vh + c * 8);
    }
}

__global__ void __launch_bounds__(128, 4) attn_mma3()
{
    extern __shared__ __align__(128) char smem[];
    uint32_t sb = smem_u32(smem);
    int tid = threadIdx.x;
    int wid = tid >> 5, lane = tid & 31;
    int bh = blockIdx.y;
    int nb = bh / H, h = bh % H;
    int q0 = blockIdx.x * 64;

    kv_prefetch(sb, bh, 0, tid);
    CP_COMMIT();

    // init constant V rows 64-71 in BOTH buffers (outside cp.async region):
    // row 64 = 1.0h, rows 65-71 = 0. 128 threads x 16B = 2048B.
    {
        int buf = tid >> 6;               // 0 or 1
        int rr = (tid >> 3) & 7;          // row offset 0..7
        int ch = tid & 7;                 // 16B chunk 0..7
        uint32_t a = sb + (uint32_t)buf * STAGE_B + VH_O
                   + (uint32_t)(64 + rr) * SKB + (uint32_t)ch * 16;
        uint32_t v = (rr == 0) ? 0x3C003C00u : 0u;
        STS128(a, v, v, v, v);
    }

    // stage Q through stage-1 KH region (transient; consumed before prefetch 1)
    {
        uint32_t q_s = sb + STAGE_B + KH_O;
        int m = tid >> 1;
        int u0 = (tid & 1) * 4;
        uint32_t o = (uint32_t)m * SKB + (uint32_t)u0 * 16;
        const uint4* s = (const uint4*)(g_qf + ((size_t)bh * Ldim + q0 + m) * HD) + u0;
        uint4 a = s[0], b = s[1], c = s[2], d = s[3];
        STS128(q_s + o,      a.x, a.y, a.z, a.w);
        STS128(q_s + o + 16, b.x, b.y, b.z, b.w);
        STS128(q_s + o + 32, c.x, c.y, c.z, c.w);
        STS128(q_s + o + 48, d.x, d.y, d.z, d.w);
    }
    __syncthreads();

    uint32_t qrow = (uint32_t)(16 * wid + (lane & 15)) * SKB + (uint32_t)(lane >> 4) * 16;
    uint32_t brow = (uint32_t)(((lane >> 4) * 8 + (lane & 7))) * SKB
                  + (uint32_t)((lane >> 3) & 1) * 16;
    uint32_t vext_row = (uint32_t)(64 + (lane & 7)) * SKB
                      + (uint32_t)((lane >> 3) & 1) * 16;

    uint32_t qf[4][4];
#pragma unroll
    for (int k = 0; k < 4; k++)
        ldm_x4(qf[k], sb + STAGE_B + KH_O + qrow + k * 32);
    __syncthreads();

    // Oa[0..7] = O columns; Oa[8] col 64 = l (ones-column accumulator)
    float Oa[9][4];
#pragma unroll
    for (int n = 0; n < 9; n++)
#pragma unroll
        for (int j = 0; j < 4; j++) Oa[n][j] = 0.f;
    float m_lo = -INFINITY, m_hi = -INFINITY;

    for (int t = 0; t < NT; t++) {
        uint32_t cb = sb + (uint32_t)(t & 1) * STAGE_B;
        if (t + 1 < NT) {
            kv_prefetch(sb + (uint32_t)((t + 1) & 1) * STAGE_B,
                        bh, (t + 1) * 64, tid);
            CP_COMMIT();
            CP_WAIT1();
        } else {
            CP_WAIT0();
        }
        __syncthreads();

        // ---- S = Q K^T (single-K) --------------------------------------------
        float c[8][4];
#pragma unroll
        for (int n = 0; n < 8; n++)
#pragma unroll
            for (int j = 0; j < 4; j++) c[n][j] = 0.f;
#pragma unroll
        for (int np = 0; np < 4; np++) {
            uint32_t baseH = cb + KH_O + brow + np * (16 * SKB);
#pragma unroll
            for (int k = 0; k < 4; k++) {
                uint32_t bhh[4];
                ldm_x4(bhh, baseH + k * 32);
                mma16816(c[2 * np],     qf[k], bhh);
                mma16816(c[2 * np + 1], qf[k], bhh + 2);
            }
        }

        // ---- online softmax (quad-local rows) -------------------------------
        float mn_lo = m_lo, mn_hi = m_hi;
#pragma unroll
        for (int n = 0; n < 8; n++) {
            mn_lo = fmaxf(mn_lo, fmaxf(c[n][0], c[n][1]));
            mn_hi = fmaxf(mn_hi, fmaxf(c[n][2], c[n][3]));
        }
        mn_lo = fmaxf(mn_lo, __shfl_xor_sync(0xffffffffu, mn_lo, 1));
        mn_lo = fmaxf(mn_lo, __shfl_xor_sync(0xffffffffu, mn_lo, 2));
        mn_hi = fmaxf(mn_hi, __shfl_xor_sync(0xffffffffu, mn_hi, 1));
        mn_hi = fmaxf(mn_hi, __shfl_xor_sync(0xffffffffu, mn_hi, 2));
        // skip rescale if no row max changed anywhere in the warp
        bool upd = (mn_lo > m_lo) || (mn_hi > m_hi);
        if (__any_sync(0xffffffffu, upd)) {
            float corr_lo = ex2f(m_lo - mn_lo);
            float corr_hi = ex2f(m_hi - mn_hi);
#pragma unroll
            for (int n = 0; n < 9; n++) {
                Oa[n][0] *= corr_lo; Oa[n][1] *= corr_lo;
                Oa[n][2] *= corr_hi; Oa[n][3] *= corr_hi;
            }
        }
        m_lo = mn_lo; m_hi = mn_hi;

        // exp -> round to fp16 P (l comes from the ones-column MMA)
        uint32_t ph[4][4];
#pragma unroll
        for (int n = 0; n < 8; n++) {
            float p0 = ex2f(c[n][0] - m_lo);
            float p1 = ex2f(c[n][1] - m_lo);
            float p2 = ex2f(c[n][2] - m_hi);
            float p3 = ex2f(c[n][3] - m_hi);
            int kc = n >> 1, o = (n & 1) * 2;
            ph[kc][o]     = pack2h(p0, p1);
            ph[kc][o + 1] = pack2h(p2, p3);
        }

        // ---- O += P V ; l += P 1 ---------------------------------------------
#pragma unroll
        for (int np = 0; np < 4; np++) {
            uint32_t baseH = cb + VH_O + brow + np * (16 * SKB);
#pragma unroll
            for (int k = 0; k < 4; k++) {
                uint32_t vhh[4];
                ldm_x4(vhh, baseH + k * 32);
                mma16816(Oa[2 * np],     ph[k], vhh);
                mma16816(Oa[2 * np + 1], ph[k], vhh + 2);
            }
        }
#pragma unroll
        for (int k = 0; k < 4; k++) {
            uint32_t ve[2];
            ldm_x2(ve, cb + VH_O + vext_row + k * 32);
            mma16816(Oa[8], ph[k], ve);
        }
        __syncthreads();
    }

    // ---- epilogue: broadcast l from quad-lane 0, normalize, fp16 pack --------
    float l_lo = __shfl_sync(0xffffffffu, Oa[8][0], lane & ~3);
    float l_hi = __shfl_sync(0xffffffffu, Oa[8][2], lane & ~3);
    float inv_lo = 1.f / l_lo, inv_hi = 1.f / l_hi;

    int r = lane >> 2, cc = (lane & 3) * 2;
    size_t base_lo = ((size_t)(q0 + 16 * wid + r) * Nb + nb) * E + h * HD;
    size_t base_hi = ((size_t)(q0 + 16 * wid + r + 8) * Nb + nb) * E + h * HD;
#pragma unroll
    for (int n = 0; n < 8; n++) {
        int d = n * 8 + cc;
        ((uint32_t*)g_of)[(base_lo + d) >> 1] =
            pack2h(Oa[n][0] * inv_lo, Oa[n][1] * inv_lo);
        ((uint32_t*)g_of)[(base_hi + d) >> 1] =
            pack2h(Oa[n][2] * inv_hi, Oa[n][3] * inv_hi);
    }
}

// ---------------- launcher ---------------------------------------------------
extern "C" void kernel_launch(void* const* d_in, const int* in_sizes, int n_in,
                              void* d_out, int out_size)
{
    const float* query = (const float*)d_in[0];
    const float* key   = (const float*)d_in[1];
    const float* value = (const float*)d_in[2];
    const float* in_w  = (const float*)d_in[3];
    const float* in_b  = (const float*)d_in[4];
    const float* q_dn  = (const float*)d_in[5];
    const float* q_up  = (const float*)d_in[6];
    const float* k_dn  = (const float*)d_in[7];
    const float* k_up  = (const float*)d_in[8];
    const float* v_dn  = (const float*)d_in[9];
    const float* v_up  = (const float*)d_in[10];
    const float* out_w = (const float*)d_in[11];
    const float* out_b = (const float*)d_in[12];
    const float* o_dn  = (const float*)d_in[13];
    const float* o_up  = (const float*)d_in[14];

    __half *p_wh, *p_xf, *p_of;
    cudaGetSymbolAddress((void**)&p_wh, g_wh);
    cudaGetSymbolAddress((void**)&p_xf, g_xf);
    cudaGetSymbolAddress((void**)&p_of, g_of);

    cudaFuncSetAttribute(attn_mma3,
                         cudaFuncAttributeMaxDynamicSharedMemorySize, S_TOTAL3);
    cudaFuncSetAttribute(gemm_mma,
                         cudaFuncAttributeMaxDynamicSharedMemorySize, G_SMEM);

    // 1) W_eff -> fp16 + input fp16 pack
    weff_split_kernel<<<WEFF_BLOCKS + XSPL_BLOCKS, 256>>>(
        in_w, out_w, q_dn, q_up, k_dn, k_up, v_dn, v_up, o_dn, o_up,
        query, key, value);
    // 2) QKV projections; q/k written in attention fp16 layout
    gemm_mma<<<dim3(E / 128, Mrows / 128, 3), 256, G_SMEM>>>(
        p_xf, p_wh, in_b, nullptr, /*mode=*/1);
    // 3) v transpose to fp16 [bh][d][L]
    v_prep<<<dim3(Ldim / 64, BH), 256>>>();
    // 4) warp-MMA flash attention (launch #4 -> profiled); writes g_of
    attn_mma3<<<dim3(Ldim / 64, BH), 128, S_TOTAL3>>>();
    // 5) output projection -> d_out (fp32)
    gemm_mma<<<dim3(E / 128, Mrows / 128, 1), 256, G_SMEM>>>(
        p_of, p_wh + 3 * (size_t)EE, out_b, (float*)d_out, /*mode=*/0);
}